// round 4
// baseline (speedup 1.0000x reference)
#include <cuda_runtime.h>
#include <cstdint>
#include <cstddef>

#define B_    4
#define S_    2048
#define D_    1024
#define H_    16
#define HD_   64
#define HALF_ 32
#define M_    (B_ * S_)   // 8192

// Scratch (allocation-free): Q/K/V in [B,H,S,HD], attention out in [B,S,D]
__device__ float g_q[B_ * S_ * D_];
__device__ float g_k[B_ * S_ * D_];
__device__ float g_v[B_ * S_ * D_];
__device__ float g_o[B_ * S_ * D_];

// ============================================================================
// GEMM: C[m,n] = sum_k A[m,k] * W[n,k]   (A row-major MxK, W row-major NxK)
// mode 0: A = x, W in {wq,wk,wv} by blockIdx.y; epilogue RoPE -> g_q/g_k/g_v
// mode 1: A = g_o, W = wo; epilogue plain -> out
// Tile 128x128x16, 256 threads, 8x8 microtile, double-buffered smem.
// ============================================================================
#define BM 128
#define BN 128
#define BK 16
#define LDA (BM + 4)

__global__ __launch_bounds__(256) void gemm_kernel(
    const float* __restrict__ x,
    const float* __restrict__ wq, const float* __restrict__ wk,
    const float* __restrict__ wv, const float* __restrict__ wo,
    const float* __restrict__ cosT, const float* __restrict__ sinT,
    float* __restrict__ out, int mode)
{
    __shared__ float As[2][BK][LDA];
    __shared__ float Bs[2][BK][LDA];

    const int tid = threadIdx.x;
    const int m0  = blockIdx.x * BM;
    const int by  = blockIdx.y;
    const int K   = 1024;

    const float* Aptr;
    const float* Bptr;
    int mat = 0;
    if (mode == 0) {
        mat  = by >> 3;   // 0:q 1:k 2:v
        Aptr = x;
        const float* W = (mat == 0) ? wq : (mat == 1 ? wk : wv);
        Bptr = W + (size_t)((by & 7) * BN) * K;
    } else {
        Aptr = g_o;
        Bptr = wo + (size_t)(by * BN) * K;
    }
    Aptr += (size_t)m0 * K;

    float acc[8][8];
    #pragma unroll
    for (int i = 0; i < 8; i++)
        #pragma unroll
        for (int j = 0; j < 8; j++) acc[i][j] = 0.0f;

    // ---- load stage 0 ----
    #pragma unroll
    for (int i = 0; i < 2; i++) {
        int lin = tid + i * 256;
        int r = lin >> 2, c4 = (lin & 3) * 4;
        float4 va = *(const float4*)(Aptr + (size_t)r * K + c4);
        float4 vb = *(const float4*)(Bptr + (size_t)r * K + c4);
        As[0][c4 + 0][r] = va.x; As[0][c4 + 1][r] = va.y;
        As[0][c4 + 2][r] = va.z; As[0][c4 + 3][r] = va.w;
        Bs[0][c4 + 0][r] = vb.x; Bs[0][c4 + 1][r] = vb.y;
        Bs[0][c4 + 2][r] = vb.z; Bs[0][c4 + 3][r] = vb.w;
    }
    __syncthreads();

    const int tm = tid >> 4, tn = tid & 15;
    const int rowB = tm * 8, colB = tn * 8;
    const int nt = K / BK; // 64

    for (int kt = 0; kt < nt; kt++) {
        const int buf = kt & 1;
        float4 pa[2], pb[2];
        if (kt + 1 < nt) {
            const int k0 = (kt + 1) * BK;
            #pragma unroll
            for (int i = 0; i < 2; i++) {
                int lin = tid + i * 256;
                int r = lin >> 2, c4 = (lin & 3) * 4;
                pa[i] = *(const float4*)(Aptr + (size_t)r * K + k0 + c4);
                pb[i] = *(const float4*)(Bptr + (size_t)r * K + k0 + c4);
            }
        }
        #pragma unroll
        for (int kk = 0; kk < BK; kk++) {
            float4 a0 = *(const float4*)&As[buf][kk][rowB];
            float4 a1 = *(const float4*)&As[buf][kk][rowB + 4];
            float4 b0 = *(const float4*)&Bs[buf][kk][colB];
            float4 b1 = *(const float4*)&Bs[buf][kk][colB + 4];
            float a[8] = {a0.x, a0.y, a0.z, a0.w, a1.x, a1.y, a1.z, a1.w};
            float b[8] = {b0.x, b0.y, b0.z, b0.w, b1.x, b1.y, b1.z, b1.w};
            #pragma unroll
            for (int i = 0; i < 8; i++)
                #pragma unroll
                for (int j = 0; j < 8; j++)
                    acc[i][j] = fmaf(a[i], b[j], acc[i][j]);
        }
        if (kt + 1 < nt) {
            const int nb = buf ^ 1;
            #pragma unroll
            for (int i = 0; i < 2; i++) {
                int lin = tid + i * 256;
                int r = lin >> 2, c4 = (lin & 3) * 4;
                As[nb][c4 + 0][r] = pa[i].x; As[nb][c4 + 1][r] = pa[i].y;
                As[nb][c4 + 2][r] = pa[i].z; As[nb][c4 + 3][r] = pa[i].w;
                Bs[nb][c4 + 0][r] = pb[i].x; Bs[nb][c4 + 1][r] = pb[i].y;
                Bs[nb][c4 + 2][r] = pb[i].z; Bs[nb][c4 + 3][r] = pb[i].w;
            }
        }
        __syncthreads();
    }

    // ---- epilogue ----
    if (mode == 1) {
        #pragma unroll
        for (int i = 0; i < 8; i++) {
            size_t m = (size_t)(m0 + rowB + i);
            float* dst = out + m * 1024 + by * BN + colB;
            *(float4*)(dst + 0) = make_float4(acc[i][0], acc[i][1], acc[i][2], acc[i][3]);
            *(float4*)(dst + 4) = make_float4(acc[i][4], acc[i][5], acc[i][6], acc[i][7]);
        }
    } else {
        const int nloc = (by & 7) * BN + colB;   // 0..1023
        const int h = nloc >> 6, hd0 = nloc & 63;
        float* dstBase = (mat == 0) ? g_q : (mat == 1 ? g_k : g_v);
        #pragma unroll
        for (int i = 0; i < 8; i++) {
            int m = m0 + rowB + i;
            int bb = m >> 11, s = m & 2047;
            float* dst = dstBase + ((size_t)(bb * H_ + h) * S_ + s) * HD_ + hd0;
            if (mat == 2) {
                *(float4*)(dst + 0) = make_float4(acc[i][0], acc[i][1], acc[i][2], acc[i][3]);
                *(float4*)(dst + 4) = make_float4(acc[i][4], acc[i][5], acc[i][6], acc[i][7]);
            } else {
                const float* cp = cosT + s * HALF_ + (hd0 >> 1);
                const float* sp = sinT + s * HALF_ + (hd0 >> 1);
                float r_[8];
                #pragma unroll
                for (int p = 0; p < 4; p++) {
                    float c = cp[p], sn = sp[p];
                    float e0 = acc[i][2 * p], e1 = acc[i][2 * p + 1];
                    r_[2 * p]     = e0 * c - e1 * sn;
                    r_[2 * p + 1] = e0 * sn + e1 * c;
                }
                *(float4*)(dst + 0) = make_float4(r_[0], r_[1], r_[2], r_[3]);
                *(float4*)(dst + 4) = make_float4(r_[4], r_[5], r_[6], r_[7]);
            }
        }
    }
}

// ============================================================================
// Flash attention, causal, fp32. BQ = BKV = 64. 8 warps, 8 query rows/warp.
// Q/K/V in [B,H,S,HD] (RoPE pre-applied). Output -> g_o in [B,S,D].
// ============================================================================
#define KS_STRIDE 68
#define FLASH_SMEM_FLOATS (64*64 + 64*KS_STRIDE + 64*64 + 64*64)
#define FLASH_SMEM_BYTES  (FLASH_SMEM_FLOATS * 4)

__global__ __launch_bounds__(256) void flash_kernel()
{
    extern __shared__ float sm[];
    float* Qs = sm;                  // [64][64]
    float* Ks = Qs + 64 * 64;        // [64][68] (padded: lane-per-key reads)
    float* Vs = Ks + 64 * KS_STRIDE; // [64][64]
    float* Ps = Vs + 64 * 64;        // [64][64] (warp-private rows)

    const int tid = threadIdx.x;
    const int qb  = blockIdx.x;     // query block (64 rows)
    const int bh  = blockIdx.y;     // b*H + h

    const float* Qg = g_q + ((size_t)bh * S_ + qb * 64) * HD_;
    const float* Kg = g_k + (size_t)bh * S_ * HD_;
    const float* Vg = g_v + (size_t)bh * S_ * HD_;

    #pragma unroll
    for (int i = 0; i < 4; i++) {
        int lin = tid + i * 256;
        int r = lin >> 4, c4 = (lin & 15) * 4;
        *(float4*)&Qs[r * 64 + c4] = *(const float4*)(Qg + (size_t)r * 64 + c4);
    }

    const int w = tid >> 5, lane = tid & 31;
    const int rbase = w * 8;

    float o0[8], o1[8], mrow[8], lrow[8];
    #pragma unroll
    for (int r = 0; r < 8; r++) { o0[r] = 0.f; o1[r] = 0.f; mrow[r] = -1e30f; lrow[r] = 0.f; }

    for (int c = 0; c <= qb; c++) {
        __syncthreads();   // all PV reads of Vs done before overwrite
        const float* Kc = Kg + (size_t)c * 64 * HD_;
        const float* Vc = Vg + (size_t)c * 64 * HD_;
        #pragma unroll
        for (int i = 0; i < 4; i++) {
            int lin = tid + i * 256;
            int r = lin >> 4, c4 = (lin & 15) * 4;
            *(float4*)&Ks[r * KS_STRIDE + c4] = *(const float4*)(Kc + (size_t)r * 64 + c4);
            *(float4*)&Vs[r * 64 + c4]        = *(const float4*)(Vc + (size_t)r * 64 + c4);
        }
        __syncthreads();

        // scores: lane owns keys (lane, lane+32), 8 rows
        float s0[8], s1[8];
        #pragma unroll
        for (int r = 0; r < 8; r++) { s0[r] = 0.f; s1[r] = 0.f; }
        const float* K0 = Ks + lane * KS_STRIDE;
        const float* K1 = Ks + (lane + 32) * KS_STRIDE;
        #pragma unroll
        for (int d4 = 0; d4 < 16; d4++) {
            float4 ka = *(const float4*)(K0 + d4 * 4);
            float4 kb = *(const float4*)(K1 + d4 * 4);
            #pragma unroll
            for (int r = 0; r < 8; r++) {
                float4 q = *(const float4*)&Qs[(rbase + r) * 64 + d4 * 4];
                s0[r] = fmaf(q.x, ka.x, fmaf(q.y, ka.y, fmaf(q.z, ka.z, fmaf(q.w, ka.w, s0[r]))));
                s1[r] = fmaf(q.x, kb.x, fmaf(q.y, kb.y, fmaf(q.z, kb.z, fmaf(q.w, kb.w, s1[r]))));
            }
        }

        const bool diag = (c == qb);
        #pragma unroll
        for (int r = 0; r < 8; r++) {
            float v0 = s0[r] * 0.125f;
            float v1 = s1[r] * 0.125f;
            if (diag) {
                int qi = rbase + r;
                if (lane > qi)      v0 = -1e30f;
                if (lane + 32 > qi) v1 = -1e30f;
            }
            float mx = fmaxf(v0, v1);
            #pragma unroll
            for (int off = 16; off; off >>= 1)
                mx = fmaxf(mx, __shfl_xor_sync(0xffffffffu, mx, off));
            float mn = fmaxf(mrow[r], mx);
            float p0 = __expf(v0 - mn);
            float p1 = __expf(v1 - mn);
            float rs = p0 + p1;
            #pragma unroll
            for (int off = 16; off; off >>= 1)
                rs += __shfl_xor_sync(0xffffffffu, rs, off);
            float alpha = __expf(mrow[r] - mn);
            lrow[r] = lrow[r] * alpha + rs;
            mrow[r] = mn;
            o0[r] *= alpha;
            o1[r] *= alpha;
            Ps[(rbase + r) * 64 + lane]      = p0;
            Ps[(rbase + r) * 64 + lane + 32] = p1;
        }
        __syncwarp();

        // PV: lane owns output dims (lane, lane+32)
        const int d0 = lane, d1 = lane + 32;
        #pragma unroll
        for (int k4 = 0; k4 < 16; k4++) {
            float va0 = Vs[(k4 * 4 + 0) * 64 + d0];
            float va1 = Vs[(k4 * 4 + 1) * 64 + d0];
            float va2 = Vs[(k4 * 4 + 2) * 64 + d0];
            float va3 = Vs[(k4 * 4 + 3) * 64 + d0];
            float vb0 = Vs[(k4 * 4 + 0) * 64 + d1];
            float vb1 = Vs[(k4 * 4 + 1) * 64 + d1];
            float vb2 = Vs[(k4 * 4 + 2) * 64 + d1];
            float vb3 = Vs[(k4 * 4 + 3) * 64 + d1];
            #pragma unroll
            for (int r = 0; r < 8; r++) {
                float4 p = *(const float4*)&Ps[(rbase + r) * 64 + k4 * 4];
                o0[r] = fmaf(p.x, va0, fmaf(p.y, va1, fmaf(p.z, va2, fmaf(p.w, va3, o0[r]))));
                o1[r] = fmaf(p.x, vb0, fmaf(p.y, vb1, fmaf(p.z, vb2, fmaf(p.w, vb3, o1[r]))));
            }
        }
        __syncwarp();   // PV reads of Ps done before next chunk's writes
    }

    const int b = bh >> 4, h = bh & 15;
    #pragma unroll
    for (int r = 0; r < 8; r++) {
        int qi = qb * 64 + rbase + r;
        float inv = 1.0f / lrow[r];
        float* dst = g_o + ((size_t)b * S_ + qi) * D_ + h * HD_;
        dst[lane]      = o0[r] * inv;
        dst[lane + 32] = o1[r] * inv;
    }
}

// ============================================================================
extern "C" void kernel_launch(void* const* d_in, const int* in_sizes, int n_in,
                              void* d_out, int out_size)
{
    (void)in_sizes; (void)n_in; (void)out_size;
    const float* x    = (const float*)d_in[0];
    const float* fcos = (const float*)d_in[1];
    const float* fsin = (const float*)d_in[2];
    const float* wq   = (const float*)d_in[3];
    const float* wk   = (const float*)d_in[4];
    const float* wv   = (const float*)d_in[5];
    const float* wo   = (const float*)d_in[6];
    float* out = (float*)d_out;

    cudaFuncSetAttribute(flash_kernel,
                         cudaFuncAttributeMaxDynamicSharedMemorySize,
                         FLASH_SMEM_BYTES);

    // 1) QKV projections + RoPE -> g_q/g_k/g_v  [B,H,S,HD]
    gemm_kernel<<<dim3(M_ / BM, 3 * D_ / BN), 256>>>(
        x, wq, wk, wv, wo, fcos, fsin, out, 0);

    // 2) causal flash attention -> g_o  [B,S,D]
    flash_kernel<<<dim3(S_ / 64, B_ * H_), 256, FLASH_SMEM_BYTES>>>();

    // 3) output projection -> d_out
    gemm_kernel<<<dim3(M_ / BM, D_ / BN), 256>>>(
        x, wq, wk, wv, wo, fcos, fsin, out, 1);
}

// round 7
// speedup vs baseline: 1.5894x; 1.5894x over previous
#include <cuda_runtime.h>
#include <cuda_bf16.h>
#include <cstdint>
#include <cstddef>

#define B_    4
#define S_    2048
#define D_    1024
#define H_    16
#define HD_   64
#define HALF_ 32
#define M_    (B_ * S_)   // 8192

// ---------------- scratch (allocation-free) ----------------
__device__ float g_q[B_ * S_ * D_];
__device__ float g_k[B_ * S_ * D_];
__device__ float g_v[B_ * S_ * D_];
__device__ float g_o[B_ * S_ * D_];
__device__ __align__(16) __nv_bfloat16 g_ahi[M_ * D_];
__device__ __align__(16) __nv_bfloat16 g_alo[M_ * D_];
__device__ __align__(16) __nv_bfloat16 g_whi[4 * D_ * D_];
__device__ __align__(16) __nv_bfloat16 g_wlo[4 * D_ * D_];

// ---------------- helpers (portable: sm_80+ PTX only) ----------------
__device__ __forceinline__ uint32_t smem_u32(const void* p) {
    uint32_t a;
    asm("{ .reg .u64 t; cvta.to.shared.u64 t, %1; cvt.u32.u64 %0, t; }" : "=r"(a) : "l"(p));
    return a;
}
__device__ __forceinline__ void cpasync16(uint32_t dst, const void* src) {
    asm volatile("cp.async.cg.shared.global [%0], [%1], 16;" :: "r"(dst), "l"(src));
}
__device__ __forceinline__ void ldm_x4(uint32_t* r, uint32_t a) {
    asm volatile("ldmatrix.sync.aligned.m8n8.x4.shared.b16 {%0,%1,%2,%3}, [%4];"
        : "=r"(r[0]), "=r"(r[1]), "=r"(r[2]), "=r"(r[3]) : "r"(a));
}
__device__ __forceinline__ void mma16816(float* d, const uint32_t* a, const uint32_t* b) {
    asm volatile("mma.sync.aligned.m16n8k16.row.col.f32.bf16.bf16.f32 "
        "{%0,%1,%2,%3}, {%4,%5,%6,%7}, {%8,%9}, {%0,%1,%2,%3};"
        : "+f"(d[0]), "+f"(d[1]), "+f"(d[2]), "+f"(d[3])
        : "r"(a[0]), "r"(a[1]), "r"(a[2]), "r"(a[3]), "r"(b[0]), "r"(b[1]));
}

// ============================================================================
// split: fp32 -> (bf16 hi, bf16 lo)
// ============================================================================
__global__ __launch_bounds__(256) void split_kernel(
    const float* __restrict__ src, __nv_bfloat16* __restrict__ hi,
    __nv_bfloat16* __restrict__ lo, int n4)
{
    int i = blockIdx.x * 256 + threadIdx.x;
    if (i >= n4) return;
    float4 v = ((const float4*)src)[i];
    __nv_bfloat16 h0 = __float2bfloat16(v.x);
    __nv_bfloat16 h1 = __float2bfloat16(v.y);
    __nv_bfloat16 h2 = __float2bfloat16(v.z);
    __nv_bfloat16 h3 = __float2bfloat16(v.w);
    __nv_bfloat16 l0 = __float2bfloat16(v.x - __bfloat162float(h0));
    __nv_bfloat16 l1 = __float2bfloat16(v.y - __bfloat162float(h1));
    __nv_bfloat16 l2 = __float2bfloat16(v.z - __bfloat162float(h2));
    __nv_bfloat16 l3 = __float2bfloat16(v.w - __bfloat162float(h3));
    ((__nv_bfloat162*)hi)[2 * i]     = __nv_bfloat162(h0, h1);
    ((__nv_bfloat162*)hi)[2 * i + 1] = __nv_bfloat162(h2, h3);
    ((__nv_bfloat162*)lo)[2 * i]     = __nv_bfloat162(l0, l1);
    ((__nv_bfloat162*)lo)[2 * i + 1] = __nv_bfloat162(l2, l3);
}

// ============================================================================
// mma.sync bf16x3-split GEMM: C[m,n] = sum_k A[m,k]*W[n,k], fp32 accum.
// Tile 128x128, BK=64, double-buffered cp.async, 256 thr (8 warps = 2m x 4n).
// Warp tile 64x32: 4 m-atoms x 4 n-atoms of m16n8k16.
// mode 0: A = x(hi/lo), W = wq/wk/wv by blockIdx.y; RoPE epilogue -> g_q/g_k/g_v
// mode 1: A = attn-out(hi/lo), W = wo; plain epilogue -> out
// ============================================================================
#define TILE_BYTES 16384               // 128 rows x 64 bf16 (=128B) per matrix
#define STAGE_BYTES (4 * TILE_BYTES)   // Ahi,Alo,Bhi,Blo = 64KB
#define GEMM_SMEM (2 * STAGE_BYTES)    // 128KB double-buffered

__global__ __launch_bounds__(256, 1) void gemm_tc(
    const __nv_bfloat16* __restrict__ Ahi_g, const __nv_bfloat16* __restrict__ Alo_g,
    const float* __restrict__ cosT, const float* __restrict__ sinT,
    float* __restrict__ out, int mode)
{
    extern __shared__ __align__(1024) char smem[];
    const uint32_t sb = smem_u32(smem);
    const int tid = threadIdx.x;
    const int wid = tid >> 5, lane = tid & 31;
    const int m0 = blockIdx.x * 128;
    const int by = blockIdx.y;

    int mat, n0;
    if (mode == 0) { mat = by >> 3; n0 = (by & 7) * 128; }
    else           { mat = 3;       n0 = by * 128; }
    const char* gsrc[4] = {
        (const char*)(Ahi_g + (size_t)m0 * D_),
        (const char*)(Alo_g + (size_t)m0 * D_),
        (const char*)(g_whi + (size_t)mat * D_ * D_ + (size_t)n0 * D_),
        (const char*)(g_wlo + (size_t)mat * D_ * D_ + (size_t)n0 * D_) };

    // loader geometry: per matrix 128 rows x 8 x 16B chunks; 4 chunks/thread/matrix
    const int l_row[4] = { tid >> 3, (tid + 256) >> 3, (tid + 512) >> 3, (tid + 768) >> 3 };
    const int l_kg = tid & 7;

    // fragment addressing (XOR-swizzled 128B rows: chunk' = chunk ^ (row&7))
    const int wm = (wid & 1) * 64;
    const int wn = (wid >> 1) * 32;
    const uint32_t a_row = wm + (lane & 15);
    const uint32_t a_co  = lane >> 4;
    const uint32_t a_sw  = a_row & 7;
    const uint32_t b_row = wn + (lane & 7) + ((lane >> 4) << 3);
    const uint32_t b_co  = (lane >> 3) & 1;
    const uint32_t b_sw  = b_row & 7;

    float acc[4][4][4];
    #pragma unroll
    for (int im = 0; im < 4; im++)
        #pragma unroll
        for (int in = 0; in < 4; in++)
            #pragma unroll
            for (int e = 0; e < 4; e++) acc[im][in][e] = 0.0f;

    // ---- async loader for one stage (k-chunk c -> buffer buf) ----
    auto load_stage = [&](int buf, int c) {
        const uint32_t sdst = sb + buf * STAGE_BYTES;
        const size_t kb = (size_t)c * 128;
        #pragma unroll
        for (int mtx = 0; mtx < 4; mtx++) {
            #pragma unroll
            for (int i = 0; i < 4; i++) {
                const int row = l_row[i];
                const char* src = gsrc[mtx] + (size_t)row * 2048 + kb + l_kg * 16;
                uint32_t dst = sdst + mtx * TILE_BYTES + row * 128
                             + ((l_kg ^ (row & 7)) << 4);
                cpasync16(dst, src);
            }
        }
    };

    load_stage(0, 0);
    asm volatile("cp.async.commit_group;" ::: "memory");
    load_stage(1, 1);
    asm volatile("cp.async.commit_group;" ::: "memory");
    asm volatile("cp.async.wait_group 1;" ::: "memory");
    __syncthreads();

    for (int c = 0; c < 16; c++) {
        const int buf = c & 1;
        const uint32_t s0 = sb + buf * STAGE_BYTES;

        #pragma unroll
        for (int ks = 0; ks < 4; ks++) {
            uint32_t ah[4][4], al[4][4], bh[2][4], bl[2][4];
            const uint32_t asw = ((2 * ks + a_co) ^ a_sw) << 4;
            const uint32_t bsw = ((2 * ks + b_co) ^ b_sw) << 4;
            #pragma unroll
            for (int im = 0; im < 4; im++) {
                const uint32_t ro = (a_row + im * 16) * 128 + asw;
                ldm_x4(ah[im], s0 + 0 * TILE_BYTES + ro);
                ldm_x4(al[im], s0 + 1 * TILE_BYTES + ro);
            }
            #pragma unroll
            for (int j = 0; j < 2; j++) {
                const uint32_t ro = (b_row + j * 16) * 128 + bsw;
                ldm_x4(bh[j], s0 + 2 * TILE_BYTES + ro);
                ldm_x4(bl[j], s0 + 3 * TILE_BYTES + ro);
            }
            #pragma unroll
            for (int im = 0; im < 4; im++)
                #pragma unroll
                for (int in = 0; in < 4; in++) {
                    const uint32_t* ph = &bh[in >> 1][(in & 1) * 2];
                    const uint32_t* pl = &bl[in >> 1][(in & 1) * 2];
                    mma16816(acc[im][in], ah[im], ph);
                    mma16816(acc[im][in], ah[im], pl);
                    mma16816(acc[im][in], al[im], ph);
                }
        }
        __syncthreads();
        if (c + 2 < 16) {
            load_stage(buf, c + 2);
            asm volatile("cp.async.commit_group;" ::: "memory");
            asm volatile("cp.async.wait_group 1;" ::: "memory");
        } else {
            asm volatile("cp.async.wait_group 0;" ::: "memory");
        }
        __syncthreads();
    }

    // ---- epilogue ----
    const int g = lane >> 2, q = lane & 3;
    #pragma unroll
    for (int im = 0; im < 4; im++) {
        #pragma unroll
        for (int half = 0; half < 2; half++) {
            const int m = m0 + wm + im * 16 + half * 8 + g;
            #pragma unroll
            for (int in = 0; in < 4; in++) {
                const int n = n0 + wn + in * 8 + q * 2;
                const float e0 = acc[im][in][half * 2 + 0];
                const float e1 = acc[im][in][half * 2 + 1];
                if (mode == 1) {
                    *(float2*)(out + (size_t)m * D_ + n) = make_float2(e0, e1);
                } else {
                    const int b = m >> 11, s = m & 2047;
                    const int h = n >> 6, hd = n & 63;
                    float* base = (mat == 0) ? g_q : (mat == 1 ? g_k : g_v);
                    float* dst = base + ((size_t)(b * H_ + h) * S_ + s) * HD_ + hd;
                    if (mat == 2) {
                        *(float2*)dst = make_float2(e0, e1);
                    } else {
                        const float cc = cosT[(size_t)s * HALF_ + (hd >> 1)];
                        const float ss = sinT[(size_t)s * HALF_ + (hd >> 1)];
                        *(float2*)dst = make_float2(e0 * cc - e1 * ss,
                                                    e0 * ss + e1 * cc);
                    }
                }
            }
        }
    }
}

// ============================================================================
// Flash attention, causal, fp32 (unchanged from passing R4 kernel).
// ============================================================================
#define KS_STRIDE 68
#define FLASH_SMEM_FLOATS (64*64 + 64*KS_STRIDE + 64*64 + 64*64)
#define FLASH_SMEM_BYTES  (FLASH_SMEM_FLOATS * 4)

__global__ __launch_bounds__(256) void flash_kernel()
{
    extern __shared__ float sm[];
    float* Qs = sm;
    float* Ks = Qs + 64 * 64;
    float* Vs = Ks + 64 * KS_STRIDE;
    float* Ps = Vs + 64 * 64;

    const int tid = threadIdx.x;
    const int qb  = blockIdx.x;
    const int bh  = blockIdx.y;

    const float* Qg = g_q + ((size_t)bh * S_ + qb * 64) * HD_;
    const float* Kg = g_k + (size_t)bh * S_ * HD_;
    const float* Vg = g_v + (size_t)bh * S_ * HD_;

    #pragma unroll
    for (int i = 0; i < 4; i++) {
        int lin = tid + i * 256;
        int r = lin >> 4, c4 = (lin & 15) * 4;
        *(float4*)&Qs[r * 64 + c4] = *(const float4*)(Qg + (size_t)r * 64 + c4);
    }

    const int w = tid >> 5, lane = tid & 31;
    const int rbase = w * 8;

    float o0[8], o1[8], mrow[8], lrow[8];
    #pragma unroll
    for (int r = 0; r < 8; r++) { o0[r] = 0.f; o1[r] = 0.f; mrow[r] = -1e30f; lrow[r] = 0.f; }

    for (int c = 0; c <= qb; c++) {
        __syncthreads();
        const float* Kc = Kg + (size_t)c * 64 * HD_;
        const float* Vc = Vg + (size_t)c * 64 * HD_;
        #pragma unroll
        for (int i = 0; i < 4; i++) {
            int lin = tid + i * 256;
            int r = lin >> 4, c4 = (lin & 15) * 4;
            *(float4*)&Ks[r * KS_STRIDE + c4] = *(const float4*)(Kc + (size_t)r * 64 + c4);
            *(float4*)&Vs[r * 64 + c4]        = *(const float4*)(Vc + (size_t)r * 64 + c4);
        }
        __syncthreads();

        float s0[8], s1[8];
        #pragma unroll
        for (int r = 0; r < 8; r++) { s0[r] = 0.f; s1[r] = 0.f; }
        const float* K0 = Ks + lane * KS_STRIDE;
        const float* K1 = Ks + (lane + 32) * KS_STRIDE;
        #pragma unroll
        for (int d4 = 0; d4 < 16; d4++) {
            float4 ka = *(const float4*)(K0 + d4 * 4);
            float4 kb = *(const float4*)(K1 + d4 * 4);
            #pragma unroll
            for (int r = 0; r < 8; r++) {
                float4 q = *(const float4*)&Qs[(rbase + r) * 64 + d4 * 4];
                s0[r] = fmaf(q.x, ka.x, fmaf(q.y, ka.y, fmaf(q.z, ka.z, fmaf(q.w, ka.w, s0[r]))));
                s1[r] = fmaf(q.x, kb.x, fmaf(q.y, kb.y, fmaf(q.z, kb.z, fmaf(q.w, kb.w, s1[r]))));
            }
        }

        const bool diag = (c == qb);
        #pragma unroll
        for (int r = 0; r < 8; r++) {
            float v0 = s0[r] * 0.125f;
            float v1 = s1[r] * 0.125f;
            if (diag) {
                int qi = rbase + r;
                if (lane > qi)      v0 = -1e30f;
                if (lane + 32 > qi) v1 = -1e30f;
            }
            float mx = fmaxf(v0, v1);
            #pragma unroll
            for (int off = 16; off; off >>= 1)
                mx = fmaxf(mx, __shfl_xor_sync(0xffffffffu, mx, off));
            float mn = fmaxf(mrow[r], mx);
            float p0 = __expf(v0 - mn);
            float p1 = __expf(v1 - mn);
            float rs = p0 + p1;
            #pragma unroll
            for (int off = 16; off; off >>= 1)
                rs += __shfl_xor_sync(0xffffffffu, rs, off);
            float alpha = __expf(mrow[r] - mn);
            lrow[r] = lrow[r] * alpha + rs;
            mrow[r] = mn;
            o0[r] *= alpha;
            o1[r] *= alpha;
            Ps[(rbase + r) * 64 + lane]      = p0;
            Ps[(rbase + r) * 64 + lane + 32] = p1;
        }
        __syncwarp();

        const int d0 = lane, d1 = lane + 32;
        #pragma unroll
        for (int k4 = 0; k4 < 16; k4++) {
            float va0 = Vs[(k4 * 4 + 0) * 64 + d0];
            float va1 = Vs[(k4 * 4 + 1) * 64 + d0];
            float va2 = Vs[(k4 * 4 + 2) * 64 + d0];
            float va3 = Vs[(k4 * 4 + 3) * 64 + d0];
            float vb0 = Vs[(k4 * 4 + 0) * 64 + d1];
            float vb1 = Vs[(k4 * 4 + 1) * 64 + d1];
            float vb2 = Vs[(k4 * 4 + 2) * 64 + d1];
            float vb3 = Vs[(k4 * 4 + 3) * 64 + d1];
            #pragma unroll
            for (int r = 0; r < 8; r++) {
                float4 p = *(const float4*)&Ps[(rbase + r) * 64 + k4 * 4];
                o0[r] = fmaf(p.x, va0, fmaf(p.y, va1, fmaf(p.z, va2, fmaf(p.w, va3, o0[r]))));
                o1[r] = fmaf(p.x, vb0, fmaf(p.y, vb1, fmaf(p.z, vb2, fmaf(p.w, vb3, o1[r]))));
            }
        }
        __syncwarp();
    }

    const int b = bh >> 4, h = bh & 15;
    #pragma unroll
    for (int r = 0; r < 8; r++) {
        int qi = qb * 64 + rbase + r;
        float inv = 1.0f / lrow[r];
        float* dst = g_o + ((size_t)b * S_ + qi) * D_ + h * HD_;
        dst[lane]      = o0[r] * inv;
        dst[lane + 32] = o1[r] * inv;
    }
}

// ============================================================================
extern "C" void kernel_launch(void* const* d_in, const int* in_sizes, int n_in,
                              void* d_out, int out_size)
{
    (void)in_sizes; (void)n_in; (void)out_size;
    const float* x    = (const float*)d_in[0];
    const float* fcos = (const float*)d_in[1];
    const float* fsin = (const float*)d_in[2];
    const float* wq   = (const float*)d_in[3];
    const float* wk   = (const float*)d_in[4];
    const float* wv   = (const float*)d_in[5];
    const float* wo   = (const float*)d_in[6];
    float* out = (float*)d_out;

    __nv_bfloat16 *p_ahi, *p_alo, *p_whi, *p_wlo;
    float* p_go;
    cudaGetSymbolAddress((void**)&p_ahi, g_ahi);
    cudaGetSymbolAddress((void**)&p_alo, g_alo);
    cudaGetSymbolAddress((void**)&p_whi, g_whi);
    cudaGetSymbolAddress((void**)&p_wlo, g_wlo);
    cudaGetSymbolAddress((void**)&p_go,  g_o);
    cudaFuncSetAttribute(flash_kernel,
                         cudaFuncAttributeMaxDynamicSharedMemorySize, FLASH_SMEM_BYTES);
    cudaFuncSetAttribute(gemm_tc,
                         cudaFuncAttributeMaxDynamicSharedMemorySize, GEMM_SMEM);

    const int n4x = M_ * D_ / 4;
    const int n4w = D_ * D_ / 4;

    // 0) fp32 -> bf16 hi/lo splits
    split_kernel<<<n4x / 256, 256>>>(x, p_ahi, p_alo, n4x);
    split_kernel<<<n4w / 256, 256>>>(wq, p_whi + 0 * D_ * D_, p_wlo + 0 * D_ * D_, n4w);
    split_kernel<<<n4w / 256, 256>>>(wk, p_whi + 1 * D_ * D_, p_wlo + 1 * D_ * D_, n4w);
    split_kernel<<<n4w / 256, 256>>>(wv, p_whi + 2 * D_ * D_, p_wlo + 2 * D_ * D_, n4w);
    split_kernel<<<n4w / 256, 256>>>(wo, p_whi + 3 * D_ * D_, p_wlo + 3 * D_ * D_, n4w);

    // 1) QKV projections + RoPE (mma.sync bf16x3) -> g_q/g_k/g_v
    gemm_tc<<<dim3(M_ / 128, 24), 256, GEMM_SMEM>>>(p_ahi, p_alo, fcos, fsin, out, 0);

    // 2) causal flash attention -> g_o
    flash_kernel<<<dim3(S_ / 64, B_ * H_), 256, FLASH_SMEM_BYTES>>>();

    // 3) split attention output, then output projection -> d_out
    split_kernel<<<n4x / 256, 256>>>(p_go, p_ahi, p_alo, n4x);
    gemm_tc<<<dim3(M_ / 128, 8), 256, GEMM_SMEM>>>(p_ahi, p_alo, fcos, fsin, out, 1);
}

// round 10
// speedup vs baseline: 3.2724x; 2.0588x over previous
#include <cuda_runtime.h>
#include <cuda_bf16.h>
#include <cuda_fp16.h>
#include <cstdint>
#include <cstddef>

#define B_    4
#define S_    2048
#define D_    1024
#define H_    16
#define HD_   64
#define HALF_ 32
#define M_    (B_ * S_)   // 8192

// ---------------- scratch (allocation-free) ----------------
__device__ float g_o[B_ * S_ * D_];                       // attention out [B,S,D]
__device__ __align__(16) __nv_bfloat16 g_ahi[M_ * D_];
__device__ __align__(16) __nv_bfloat16 g_alo[M_ * D_];
__device__ __align__(16) __nv_bfloat16 g_whi[4 * D_ * D_];
__device__ __align__(16) __nv_bfloat16 g_wlo[4 * D_ * D_];
// attention operands, [B,H,S,HD] (Q pre-scaled by 1/8, RoPE applied)
__device__ __align__(16) __nv_bfloat16 g_qhi[M_ * D_];
__device__ __align__(16) __nv_bfloat16 g_qlo[M_ * D_];
__device__ __align__(16) __nv_bfloat16 g_khi[M_ * D_];
__device__ __align__(16) __nv_bfloat16 g_klo[M_ * D_];
__device__ __align__(16) __half        g_vb [M_ * D_];    // V in fp16

// ---------------- helpers (sm_80+ portable PTX only) ----------------
__device__ __forceinline__ uint32_t smem_u32(const void* p) {
    uint32_t a;
    asm("{ .reg .u64 t; cvta.to.shared.u64 t, %1; cvt.u32.u64 %0, t; }" : "=r"(a) : "l"(p));
    return a;
}
__device__ __forceinline__ void cpasync16(uint32_t dst, const void* src) {
    asm volatile("cp.async.cg.shared.global [%0], [%1], 16;" :: "r"(dst), "l"(src));
}
__device__ __forceinline__ void ldm_x4(uint32_t* r, uint32_t a) {
    asm volatile("ldmatrix.sync.aligned.m8n8.x4.shared.b16 {%0,%1,%2,%3}, [%4];"
        : "=r"(r[0]), "=r"(r[1]), "=r"(r[2]), "=r"(r[3]) : "r"(a));
}
__device__ __forceinline__ void ldm_x4_t(uint32_t* r, uint32_t a) {
    asm volatile("ldmatrix.sync.aligned.m8n8.x4.trans.shared.b16 {%0,%1,%2,%3}, [%4];"
        : "=r"(r[0]), "=r"(r[1]), "=r"(r[2]), "=r"(r[3]) : "r"(a));
}
__device__ __forceinline__ void mma16816(float* d, const uint32_t* a, const uint32_t* b) {
    asm volatile("mma.sync.aligned.m16n8k16.row.col.f32.bf16.bf16.f32 "
        "{%0,%1,%2,%3}, {%4,%5,%6,%7}, {%8,%9}, {%0,%1,%2,%3};"
        : "+f"(d[0]), "+f"(d[1]), "+f"(d[2]), "+f"(d[3])
        : "r"(a[0]), "r"(a[1]), "r"(a[2]), "r"(a[3]), "r"(b[0]), "r"(b[1]));
}
__device__ __forceinline__ void mma16816h(float* d, const uint32_t* a, const uint32_t* b) {
    asm volatile("mma.sync.aligned.m16n8k16.row.col.f32.f16.f16.f32 "
        "{%0,%1,%2,%3}, {%4,%5,%6,%7}, {%8,%9}, {%0,%1,%2,%3};"
        : "+f"(d[0]), "+f"(d[1]), "+f"(d[2]), "+f"(d[3])
        : "r"(a[0]), "r"(a[1]), "r"(a[2]), "r"(a[3]), "r"(b[0]), "r"(b[1]));
}
#define CP_COMMIT() asm volatile("cp.async.commit_group;" ::: "memory")
#define CP_WAIT(n)  asm volatile("cp.async.wait_group %0;" :: "n"(n) : "memory")

// ============================================================================
// split: fp32 -> (bf16 hi, bf16 lo)
// ============================================================================
__global__ __launch_bounds__(256) void split_kernel(
    const float* __restrict__ src, __nv_bfloat16* __restrict__ hi,
    __nv_bfloat16* __restrict__ lo, int n4)
{
    int i = blockIdx.x * 256 + threadIdx.x;
    if (i >= n4) return;
    float4 v = ((const float4*)src)[i];
    __nv_bfloat16 h0 = __float2bfloat16(v.x);
    __nv_bfloat16 h1 = __float2bfloat16(v.y);
    __nv_bfloat16 h2 = __float2bfloat16(v.z);
    __nv_bfloat16 h3 = __float2bfloat16(v.w);
    __nv_bfloat16 l0 = __float2bfloat16(v.x - __bfloat162float(h0));
    __nv_bfloat16 l1 = __float2bfloat16(v.y - __bfloat162float(h1));
    __nv_bfloat16 l2 = __float2bfloat16(v.z - __bfloat162float(h2));
    __nv_bfloat16 l3 = __float2bfloat16(v.w - __bfloat162float(h3));
    ((__nv_bfloat162*)hi)[2 * i]     = __nv_bfloat162(h0, h1);
    ((__nv_bfloat162*)hi)[2 * i + 1] = __nv_bfloat162(h2, h3);
    ((__nv_bfloat162*)lo)[2 * i]     = __nv_bfloat162(l0, l1);
    ((__nv_bfloat162*)lo)[2 * i + 1] = __nv_bfloat162(l2, l3);
}

// ============================================================================
// mma.sync bf16x3-split GEMM
// mode 0: A = x(hi/lo), W = wq/wk/wv; RoPE epilogue -> bf16 q/k splits, fp16 v
// mode 1: A = attn-out(hi/lo), W = wo; plain epilogue -> out
// ============================================================================
#define TILE_BYTES 16384
#define STAGE_BYTES (4 * TILE_BYTES)
#define GEMM_SMEM (2 * STAGE_BYTES)

__global__ __launch_bounds__(256, 1) void gemm_tc(
    const __nv_bfloat16* __restrict__ Ahi_g, const __nv_bfloat16* __restrict__ Alo_g,
    const float* __restrict__ cosT, const float* __restrict__ sinT,
    float* __restrict__ out, int mode)
{
    extern __shared__ __align__(1024) char smem[];
    const uint32_t sb = smem_u32(smem);
    const int tid = threadIdx.x;
    const int wid = tid >> 5, lane = tid & 31;
    const int m0 = blockIdx.x * 128;
    const int by = blockIdx.y;

    int mat, n0;
    if (mode == 0) { mat = by >> 3; n0 = (by & 7) * 128; }
    else           { mat = 3;       n0 = by * 128; }
    const char* gsrc[4] = {
        (const char*)(Ahi_g + (size_t)m0 * D_),
        (const char*)(Alo_g + (size_t)m0 * D_),
        (const char*)(g_whi + (size_t)mat * D_ * D_ + (size_t)n0 * D_),
        (const char*)(g_wlo + (size_t)mat * D_ * D_ + (size_t)n0 * D_) };

    const int l_row[4] = { tid >> 3, (tid + 256) >> 3, (tid + 512) >> 3, (tid + 768) >> 3 };
    const int l_kg = tid & 7;

    const int wm = (wid & 1) * 64;
    const int wn = (wid >> 1) * 32;
    const uint32_t a_row = wm + (lane & 15);
    const uint32_t a_co  = lane >> 4;
    const uint32_t a_sw  = a_row & 7;
    const uint32_t b_row = wn + (lane & 7) + ((lane >> 4) << 3);
    const uint32_t b_co  = (lane >> 3) & 1;
    const uint32_t b_sw  = b_row & 7;

    float acc[4][4][4];
    #pragma unroll
    for (int im = 0; im < 4; im++)
        #pragma unroll
        for (int in = 0; in < 4; in++)
            #pragma unroll
            for (int e = 0; e < 4; e++) acc[im][in][e] = 0.0f;

    auto load_stage = [&](int buf, int c) {
        const uint32_t sdst = sb + buf * STAGE_BYTES;
        const size_t kb = (size_t)c * 128;
        #pragma unroll
        for (int mtx = 0; mtx < 4; mtx++) {
            #pragma unroll
            for (int i = 0; i < 4; i++) {
                const int row = l_row[i];
                const char* src = gsrc[mtx] + (size_t)row * 2048 + kb + l_kg * 16;
                uint32_t dst = sdst + mtx * TILE_BYTES + row * 128
                             + ((l_kg ^ (row & 7)) << 4);
                cpasync16(dst, src);
            }
        }
    };

    load_stage(0, 0);  CP_COMMIT();
    load_stage(1, 1);  CP_COMMIT();
    CP_WAIT(1);
    __syncthreads();

    for (int c = 0; c < 16; c++) {
        const int buf = c & 1;
        const uint32_t s0 = sb + buf * STAGE_BYTES;

        #pragma unroll
        for (int ks = 0; ks < 4; ks++) {
            uint32_t ah[4][4], al[4][4], bh[2][4], bl[2][4];
            const uint32_t asw = ((2 * ks + a_co) ^ a_sw) << 4;
            const uint32_t bsw = ((2 * ks + b_co) ^ b_sw) << 4;
            #pragma unroll
            for (int im = 0; im < 4; im++) {
                const uint32_t ro = (a_row + im * 16) * 128 + asw;
                ldm_x4(ah[im], s0 + 0 * TILE_BYTES + ro);
                ldm_x4(al[im], s0 + 1 * TILE_BYTES + ro);
            }
            #pragma unroll
            for (int j = 0; j < 2; j++) {
                const uint32_t ro = (b_row + j * 16) * 128 + bsw;
                ldm_x4(bh[j], s0 + 2 * TILE_BYTES + ro);
                ldm_x4(bl[j], s0 + 3 * TILE_BYTES + ro);
            }
            #pragma unroll
            for (int im = 0; im < 4; im++)
                #pragma unroll
                for (int in = 0; in < 4; in++) {
                    const uint32_t* ph = &bh[in >> 1][(in & 1) * 2];
                    const uint32_t* pl = &bl[in >> 1][(in & 1) * 2];
                    mma16816(acc[im][in], ah[im], ph);
                    mma16816(acc[im][in], ah[im], pl);
                    mma16816(acc[im][in], al[im], ph);
                }
        }
        __syncthreads();
        if (c + 2 < 16) {
            load_stage(buf, c + 2);
            CP_COMMIT();
            CP_WAIT(1);
        } else {
            CP_WAIT(0);
        }
        __syncthreads();
    }

    // ---- epilogue ----
    const int g = lane >> 2, q = lane & 3;
    #pragma unroll
    for (int im = 0; im < 4; im++) {
        #pragma unroll
        for (int half = 0; half < 2; half++) {
            const int m = m0 + wm + im * 16 + half * 8 + g;
            #pragma unroll
            for (int in = 0; in < 4; in++) {
                const int n = n0 + wn + in * 8 + q * 2;
                const float e0 = acc[im][in][half * 2 + 0];
                const float e1 = acc[im][in][half * 2 + 1];
                if (mode == 1) {
                    *(float2*)(out + (size_t)m * D_ + n) = make_float2(e0, e1);
                } else {
                    const int b = m >> 11, s = m & 2047;
                    const int h = n >> 6, hd = n & 63;
                    const size_t idx = ((size_t)(b * H_ + h) * S_ + s) * HD_ + hd;
                    if (mat == 2) {
                        *(__half2*)(g_vb + idx) = __floats2half2_rn(e0, e1);
                    } else {
                        const float cc = cosT[(size_t)s * HALF_ + (hd >> 1)];
                        const float ss = sinT[(size_t)s * HALF_ + (hd >> 1)];
                        float r0 = e0 * cc - e1 * ss;
                        float r1 = e0 * ss + e1 * cc;
                        if (mat == 0) { r0 *= 0.125f; r1 *= 0.125f; }  // fold 1/sqrt(HD)
                        __nv_bfloat16 h0 = __float2bfloat16(r0);
                        __nv_bfloat16 h1 = __float2bfloat16(r1);
                        __nv_bfloat16 l0 = __float2bfloat16(r0 - __bfloat162float(h0));
                        __nv_bfloat16 l1 = __float2bfloat16(r1 - __bfloat162float(h1));
                        __nv_bfloat16* hip = (mat == 0) ? g_qhi : g_khi;
                        __nv_bfloat16* lop = (mat == 0) ? g_qlo : g_klo;
                        *(__nv_bfloat162*)(hip + idx) = __nv_bfloat162(h0, h1);
                        *(__nv_bfloat162*)(lop + idx) = __nv_bfloat162(l0, l1);
                    }
                }
            }
        }
    }
}

// ============================================================================
// Flash attention on mma.sync: BQ=128, BKV=64, 8 warps x 16 q-rows.
// Scores = Qhi.Khi + Qhi.Klo + Qlo.Khi (bf16 3-split, fp32 acc, Q prescaled).
// P,V in fp16 (consistent-l), V^T via ldmatrix.trans. Out -> g_o [B,S,D].
// ============================================================================
#define FQ_HI 0
#define FQ_LO 16384
#define FKV0  32768
#define FSTG  24576
#define FKHI  0
#define FKLO  8192
#define FVV   16384
#define FLASH_SMEM (32768 + 2 * FSTG)   // 80 KB

__global__ __launch_bounds__(256, 1) void flash_mma()
{
    extern __shared__ __align__(1024) char smem[];
    const uint32_t sb = smem_u32(smem);
    const int tid = threadIdx.x, wid = tid >> 5, lane = tid & 31;
    const int qb = (int)gridDim.x - 1 - (int)blockIdx.x;  // heavy blocks first
    const int bh = blockIdx.y;
    const int nc = 2 * qb + 2;
    const int wq0 = wid * 16;

    const char* qh_g = (const char*)g_qhi + ((size_t)bh * S_ + (size_t)qb * 128) * 128;
    const char* ql_g = (const char*)g_qlo + ((size_t)bh * S_ + (size_t)qb * 128) * 128;
    const char* kh_g = (const char*)g_khi + (size_t)bh * S_ * 128;
    const char* kl_g = (const char*)g_klo + (size_t)bh * S_ * 128;
    const char* vv_g = (const char*)g_vb  + (size_t)bh * S_ * 128;

    const int kg = tid & 7;
    // Q tiles (hi+lo)
    #pragma unroll
    for (int p = 0; p < 4; p++) {
        const int row = (tid + p * 256) >> 3;   // 0..127
        const uint32_t so = row * 128 + ((kg ^ (row & 7)) << 4);
        const size_t go = (size_t)row * 128 + kg * 16;
        cpasync16(sb + FQ_HI + so, qh_g + go);
        cpasync16(sb + FQ_LO + so, ql_g + go);
    }
    CP_COMMIT();

    auto load_kv = [&](int st, int c) {
        const uint32_t base = sb + FKV0 + st * FSTG;
        #pragma unroll
        for (int p = 0; p < 2; p++) {
            const int row = (tid + p * 256) >> 3;   // 0..63
            const size_t go = ((size_t)c * 64 + row) * 128 + kg * 16;
            const uint32_t so = row * 128 + ((kg ^ (row & 7)) << 4);
            cpasync16(base + FKHI + so, kh_g + go);
            cpasync16(base + FKLO + so, kl_g + go);
            cpasync16(base + FVV  + so, vv_g + go);
        }
    };
    load_kv(0, 0);  CP_COMMIT();
    load_kv(1, 1);  CP_COMMIT();

    // Q fragments (held across the whole loop)
    CP_WAIT(2);
    __syncthreads();
    uint32_t qh[4][4], ql[4][4];
    {
        const uint32_t a_row = wq0 + (lane & 15);
        const uint32_t a_co  = lane >> 4;
        #pragma unroll
        for (int ks = 0; ks < 4; ks++) {
            const uint32_t ro = a_row * 128 + (((2 * ks + a_co) ^ (a_row & 7)) << 4);
            ldm_x4(qh[ks], sb + FQ_HI + ro);
            ldm_x4(ql[ks], sb + FQ_LO + ro);
        }
    }

    const int g = lane >> 2, q2 = (lane & 3) * 2;
    float o[8][4];
    #pragma unroll
    for (int j = 0; j < 8; j++)
        #pragma unroll
        for (int e = 0; e < 4; e++) o[j][e] = 0.0f;
    float m0r = -1e30f, m1r = -1e30f, l0r = 0.0f, l1r = 0.0f;

    const uint32_t b_row = (lane & 7) + ((lane >> 4) << 3);
    const uint32_t b_co  = (lane >> 3) & 1;
    const uint32_t v_row = lane & 15;
    const uint32_t v_co  = lane >> 4;

    for (int c = 0; c < nc; c++) {
        const int st = c & 1;
        const uint32_t kbase = sb + FKV0 + st * FSTG;
        CP_WAIT(1);
        __syncthreads();

        // ---- scores: 16 x 64, bf16 3-split ----
        float sc[8][4];
        #pragma unroll
        for (int j = 0; j < 8; j++)
            #pragma unroll
            for (int e = 0; e < 4; e++) sc[j][e] = 0.0f;

        #pragma unroll
        for (int ks = 0; ks < 4; ks++) {
            #pragma unroll
            for (int t = 0; t < 4; t++) {
                uint32_t kh4[4], kl4[4];
                const uint32_t row = b_row + 16 * t;
                const uint32_t ro = row * 128 + (((2 * ks + b_co) ^ (row & 7)) << 4);
                ldm_x4(kh4, kbase + FKHI + ro);
                ldm_x4(kl4, kbase + FKLO + ro);
                mma16816(sc[2 * t],     qh[ks], &kh4[0]);
                mma16816(sc[2 * t],     qh[ks], &kl4[0]);
                mma16816(sc[2 * t],     ql[ks], &kh4[0]);
                mma16816(sc[2 * t + 1], qh[ks], &kh4[2]);
                mma16816(sc[2 * t + 1], qh[ks], &kl4[2]);
                mma16816(sc[2 * t + 1], ql[ks], &kh4[2]);
            }
        }

        // ---- causal mask (diagonal chunks only) ----
        if (c >= 2 * qb) {
            const int kvb = c * 64;
            const int r0 = qb * 128 + wq0 + g, r1 = r0 + 8;
            #pragma unroll
            for (int j = 0; j < 8; j++) {
                const int col = kvb + 8 * j + q2;
                if (col     > r0) sc[j][0] = -1e30f;
                if (col + 1 > r0) sc[j][1] = -1e30f;
                if (col     > r1) sc[j][2] = -1e30f;
                if (col + 1 > r1) sc[j][3] = -1e30f;
            }
        }

        // ---- online softmax ----
        float mx0 = -1e30f, mx1 = -1e30f;
        #pragma unroll
        for (int j = 0; j < 8; j++) {
            mx0 = fmaxf(mx0, fmaxf(sc[j][0], sc[j][1]));
            mx1 = fmaxf(mx1, fmaxf(sc[j][2], sc[j][3]));
        }
        mx0 = fmaxf(mx0, __shfl_xor_sync(0xffffffffu, mx0, 1));
        mx0 = fmaxf(mx0, __shfl_xor_sync(0xffffffffu, mx0, 2));
        mx1 = fmaxf(mx1, __shfl_xor_sync(0xffffffffu, mx1, 1));
        mx1 = fmaxf(mx1, __shfl_xor_sync(0xffffffffu, mx1, 2));
        const float mn0 = fmaxf(m0r, mx0), mn1 = fmaxf(m1r, mx1);
        const float al0 = __expf(m0r - mn0), al1 = __expf(m1r - mn1);

        uint32_t pa[8][2];
        float rs0 = 0.0f, rs1 = 0.0f;
        #pragma unroll
        for (int j = 0; j < 8; j++) {
            const float p0 = __expf(sc[j][0] - mn0);
            const float p1 = __expf(sc[j][1] - mn0);
            const float p2 = __expf(sc[j][2] - mn1);
            const float p3 = __expf(sc[j][3] - mn1);
            __half2 h01 = __floats2half2_rn(p0, p1);
            __half2 h23 = __floats2half2_rn(p2, p3);
            pa[j][0] = *(uint32_t*)&h01;
            pa[j][1] = *(uint32_t*)&h23;
            rs0 += __low2float(h01) + __high2float(h01);
            rs1 += __low2float(h23) + __high2float(h23);
        }
        rs0 += __shfl_xor_sync(0xffffffffu, rs0, 1);
        rs0 += __shfl_xor_sync(0xffffffffu, rs0, 2);
        rs1 += __shfl_xor_sync(0xffffffffu, rs1, 1);
        rs1 += __shfl_xor_sync(0xffffffffu, rs1, 2);
        l0r = l0r * al0 + rs0;
        l1r = l1r * al1 + rs1;
        m0r = mn0; m1r = mn1;
        #pragma unroll
        for (int j = 0; j < 8; j++) {
            o[j][0] *= al0; o[j][1] *= al0;
            o[j][2] *= al1; o[j][3] *= al1;
        }

        // ---- PV: P (fp16 regs) x V^T (fp16, ldmatrix.trans) ----
        #pragma unroll
        for (int t = 0; t < 4; t++) {
            const uint32_t pA[4] = { pa[2*t][0], pa[2*t][1], pa[2*t+1][0], pa[2*t+1][1] };
            const uint32_t row = v_row + 16 * t;
            #pragma unroll
            for (int u = 0; u < 4; u++) {
                uint32_t vt[4];
                const uint32_t ro = row * 128 + (((2 * u + v_co) ^ (row & 7)) << 4);
                ldm_x4_t(vt, kbase + FVV + ro);
                mma16816h(o[2 * u],     pA, &vt[0]);
                mma16816h(o[2 * u + 1], pA, &vt[2]);
            }
        }

        __syncthreads();
        if (c + 2 < nc) load_kv(st, c + 2);
        CP_COMMIT();
    }

    // ---- epilogue -> g_o [B,S,D] ----
    const int b = bh >> 4, h = bh & 15;
    const float i0 = 1.0f / l0r, i1 = 1.0f / l1r;
    const int s0 = qb * 128 + wq0 + g, s1 = s0 + 8;
    float* d0 = g_o + ((size_t)b * S_ + s0) * D_ + h * HD_;
    float* d1 = g_o + ((size_t)b * S_ + s1) * D_ + h * HD_;
    #pragma unroll
    for (int j = 0; j < 8; j++) {
        *(float2*)(d0 + 8 * j + q2) = make_float2(o[j][0] * i0, o[j][1] * i0);
        *(float2*)(d1 + 8 * j + q2) = make_float2(o[j][2] * i1, o[j][3] * i1);
    }
}

// ============================================================================
extern "C" void kernel_launch(void* const* d_in, const int* in_sizes, int n_in,
                              void* d_out, int out_size)
{
    (void)in_sizes; (void)n_in; (void)out_size;
    const float* x    = (const float*)d_in[0];
    const float* fcos = (const float*)d_in[1];
    const float* fsin = (const float*)d_in[2];
    const float* wq   = (const float*)d_in[3];
    const float* wk   = (const float*)d_in[4];
    const float* wv   = (const float*)d_in[5];
    const float* wo   = (const float*)d_in[6];
    float* out = (float*)d_out;

    __nv_bfloat16 *p_ahi, *p_alo, *p_whi, *p_wlo;
    float* p_go;
    cudaGetSymbolAddress((void**)&p_ahi, g_ahi);
    cudaGetSymbolAddress((void**)&p_alo, g_alo);
    cudaGetSymbolAddress((void**)&p_whi, g_whi);
    cudaGetSymbolAddress((void**)&p_wlo, g_wlo);
    cudaGetSymbolAddress((void**)&p_go,  g_o);
    cudaFuncSetAttribute(gemm_tc,
                         cudaFuncAttributeMaxDynamicSharedMemorySize, GEMM_SMEM);
    cudaFuncSetAttribute(flash_mma,
                         cudaFuncAttributeMaxDynamicSharedMemorySize, FLASH_SMEM);

    const int n4x = M_ * D_ / 4;
    const int n4w = D_ * D_ / 4;

    // 0) fp32 -> bf16 hi/lo splits
    split_kernel<<<n4x / 256, 256>>>(x, p_ahi, p_alo, n4x);
    split_kernel<<<n4w / 256, 256>>>(wq, p_whi + 0 * D_ * D_, p_wlo + 0 * D_ * D_, n4w);
    split_kernel<<<n4w / 256, 256>>>(wk, p_whi + 1 * D_ * D_, p_wlo + 1 * D_ * D_, n4w);
    split_kernel<<<n4w / 256, 256>>>(wv, p_whi + 2 * D_ * D_, p_wlo + 2 * D_ * D_, n4w);
    split_kernel<<<n4w / 256, 256>>>(wo, p_whi + 3 * D_ * D_, p_wlo + 3 * D_ * D_, n4w);

    // 1) QKV projections + RoPE -> attention operands (bf16 splits + fp16 V)
    gemm_tc<<<dim3(M_ / 128, 24), 256, GEMM_SMEM>>>(p_ahi, p_alo, fcos, fsin, out, 0);

    // 2) causal flash attention (tensor cores) -> g_o
    flash_mma<<<dim3(S_ / 128, B_ * H_), 256, FLASH_SMEM>>>();

    // 3) split attention output, then output projection -> d_out
    split_kernel<<<n4x / 256, 256>>>(p_go, p_ahi, p_alo, n4x);
    gemm_tc<<<dim3(M_ / 128, 8), 256, GEMM_SMEM>>>(p_ahi, p_alo, fcos, fsin, out, 1);
}

// round 11
// speedup vs baseline: 3.3249x; 1.0161x over previous
#include <cuda_runtime.h>
#include <cuda_bf16.h>
#include <cuda_fp16.h>
#include <cstdint>
#include <cstddef>

#define B_    4
#define S_    2048
#define D_    1024
#define H_    16
#define HD_   64
#define HALF_ 32
#define M_    (B_ * S_)   // 8192

// ---------------- scratch (allocation-free) ----------------
__device__ __align__(16) __nv_bfloat16 g_ahi[M_ * D_];
__device__ __align__(16) __nv_bfloat16 g_alo[M_ * D_];
__device__ __align__(16) __nv_bfloat16 g_whi[4 * D_ * D_];
__device__ __align__(16) __nv_bfloat16 g_wlo[4 * D_ * D_];
// attention operands, [B,H,S,HD] (Q pre-scaled by 1/8, RoPE applied)
__device__ __align__(16) __nv_bfloat16 g_qhi[M_ * D_];
__device__ __align__(16) __nv_bfloat16 g_qlo[M_ * D_];
__device__ __align__(16) __nv_bfloat16 g_khi[M_ * D_];
__device__ __align__(16) __nv_bfloat16 g_klo[M_ * D_];
__device__ __align__(16) __half        g_vb [M_ * D_];    // V in fp16

// ---------------- helpers (sm_80+ portable PTX only) ----------------
__device__ __forceinline__ uint32_t smem_u32(const void* p) {
    uint32_t a;
    asm("{ .reg .u64 t; cvta.to.shared.u64 t, %1; cvt.u32.u64 %0, t; }" : "=r"(a) : "l"(p));
    return a;
}
__device__ __forceinline__ void cpasync16(uint32_t dst, const void* src) {
    asm volatile("cp.async.cg.shared.global [%0], [%1], 16;" :: "r"(dst), "l"(src));
}
__device__ __forceinline__ void ldm_x4(uint32_t* r, uint32_t a) {
    asm volatile("ldmatrix.sync.aligned.m8n8.x4.shared.b16 {%0,%1,%2,%3}, [%4];"
        : "=r"(r[0]), "=r"(r[1]), "=r"(r[2]), "=r"(r[3]) : "r"(a));
}
__device__ __forceinline__ void ldm_x4_t(uint32_t* r, uint32_t a) {
    asm volatile("ldmatrix.sync.aligned.m8n8.x4.trans.shared.b16 {%0,%1,%2,%3}, [%4];"
        : "=r"(r[0]), "=r"(r[1]), "=r"(r[2]), "=r"(r[3]) : "r"(a));
}
__device__ __forceinline__ void mma16816(float* d, const uint32_t* a, const uint32_t* b) {
    asm volatile("mma.sync.aligned.m16n8k16.row.col.f32.bf16.bf16.f32 "
        "{%0,%1,%2,%3}, {%4,%5,%6,%7}, {%8,%9}, {%0,%1,%2,%3};"
        : "+f"(d[0]), "+f"(d[1]), "+f"(d[2]), "+f"(d[3])
        : "r"(a[0]), "r"(a[1]), "r"(a[2]), "r"(a[3]), "r"(b[0]), "r"(b[1]));
}
__device__ __forceinline__ void mma16816h(float* d, const uint32_t* a, const uint32_t* b) {
    asm volatile("mma.sync.aligned.m16n8k16.row.col.f32.f16.f16.f32 "
        "{%0,%1,%2,%3}, {%4,%5,%6,%7}, {%8,%9}, {%0,%1,%2,%3};"
        : "+f"(d[0]), "+f"(d[1]), "+f"(d[2]), "+f"(d[3])
        : "r"(a[0]), "r"(a[1]), "r"(a[2]), "r"(a[3]), "r"(b[0]), "r"(b[1]));
}
#define CP_COMMIT() asm volatile("cp.async.commit_group;" ::: "memory")
#define CP_WAIT(n)  asm volatile("cp.async.wait_group %0;" :: "n"(n) : "memory")

__device__ __forceinline__ void split_one(float v, __nv_bfloat16& h, __nv_bfloat16& l) {
    h = __float2bfloat16(v);
    l = __float2bfloat16(v - __bfloat162float(h));
}

// ============================================================================
// split: fp32 -> (bf16 hi, bf16 lo)
// ============================================================================
__global__ __launch_bounds__(256) void split_kernel(
    const float* __restrict__ src, __nv_bfloat16* __restrict__ hi,
    __nv_bfloat16* __restrict__ lo, int n4)
{
    int i = blockIdx.x * 256 + threadIdx.x;
    if (i >= n4) return;
    float4 v = ((const float4*)src)[i];
    __nv_bfloat16 h0, h1, h2, h3, l0, l1, l2, l3;
    split_one(v.x, h0, l0); split_one(v.y, h1, l1);
    split_one(v.z, h2, l2); split_one(v.w, h3, l3);
    ((__nv_bfloat162*)hi)[2 * i]     = __nv_bfloat162(h0, h1);
    ((__nv_bfloat162*)hi)[2 * i + 1] = __nv_bfloat162(h2, h3);
    ((__nv_bfloat162*)lo)[2 * i]     = __nv_bfloat162(l0, l1);
    ((__nv_bfloat162*)lo)[2 * i + 1] = __nv_bfloat162(l2, l3);
}

// all 4 weights in one launch (grid.y selects matrix)
__global__ __launch_bounds__(256) void split4_kernel(
    const float* __restrict__ w0, const float* __restrict__ w1,
    const float* __restrict__ w2, const float* __restrict__ w3, int n4)
{
    const int m = blockIdx.y;
    const float* src = (m == 0) ? w0 : (m == 1) ? w1 : (m == 2) ? w2 : w3;
    __nv_bfloat16* hi = g_whi + (size_t)m * D_ * D_;
    __nv_bfloat16* lo = g_wlo + (size_t)m * D_ * D_;
    int i = blockIdx.x * 256 + threadIdx.x;
    if (i >= n4) return;
    float4 v = ((const float4*)src)[i];
    __nv_bfloat16 h0, h1, h2, h3, l0, l1, l2, l3;
    split_one(v.x, h0, l0); split_one(v.y, h1, l1);
    split_one(v.z, h2, l2); split_one(v.w, h3, l3);
    ((__nv_bfloat162*)hi)[2 * i]     = __nv_bfloat162(h0, h1);
    ((__nv_bfloat162*)hi)[2 * i + 1] = __nv_bfloat162(h2, h3);
    ((__nv_bfloat162*)lo)[2 * i]     = __nv_bfloat162(l0, l1);
    ((__nv_bfloat162*)lo)[2 * i + 1] = __nv_bfloat162(l2, l3);
}

// ============================================================================
// mma.sync bf16x3-split GEMM. Tile 256x128, BK=64, 512 thr (16 warps = 4m x 4n),
// warp tile 64x32, double-buffered cp.async, 192KB smem.
// mode 0: A = x(hi/lo), W = wq/wk/wv; RoPE epilogue -> bf16 q/k splits, fp16 v
// mode 1: A = attn-out(hi/lo) [written by flash], W = wo; plain -> out
// ============================================================================
#define STG_AHI 0
#define STG_ALO 32768
#define STG_BHI 65536
#define STG_BLO 81920
#define STG_BYTES 98304
#define GEMM_SMEM (2 * STG_BYTES)   // 192 KB

__global__ __launch_bounds__(512, 1) void gemm_tc(
    const __nv_bfloat16* __restrict__ Ahi_g, const __nv_bfloat16* __restrict__ Alo_g,
    const float* __restrict__ cosT, const float* __restrict__ sinT,
    float* __restrict__ out, int mode)
{
    extern __shared__ __align__(1024) char smem[];
    const uint32_t sb = smem_u32(smem);
    const int tid = threadIdx.x;
    const int wid = tid >> 5, lane = tid & 31;
    const int m0 = blockIdx.x * 256;
    const int by = blockIdx.y;

    int mat, n0;
    if (mode == 0) { mat = by >> 3; n0 = (by & 7) * 128; }
    else           { mat = 3;       n0 = by * 128; }
    const char* a_hi = (const char*)(Ahi_g + (size_t)m0 * D_);
    const char* a_lo = (const char*)(Alo_g + (size_t)m0 * D_);
    const char* b_hi = (const char*)(g_whi + (size_t)mat * D_ * D_ + (size_t)n0 * D_);
    const char* b_lo = (const char*)(g_wlo + (size_t)mat * D_ * D_ + (size_t)n0 * D_);

    const int l_kg = tid & 7;
    const int l_rb = tid >> 3;            // 0..63

    const int wm = (wid & 3) * 64;
    const int wn = (wid >> 2) * 32;
    const uint32_t a_row = wm + (lane & 15);
    const uint32_t a_co  = lane >> 4;
    const uint32_t a_sw  = a_row & 7;
    const uint32_t b_row = wn + (lane & 7) + ((lane >> 4) << 3);
    const uint32_t b_co  = (lane >> 3) & 1;
    const uint32_t b_sw  = b_row & 7;

    float acc[4][4][4];
    #pragma unroll
    for (int im = 0; im < 4; im++)
        #pragma unroll
        for (int in = 0; in < 4; in++)
            #pragma unroll
            for (int e = 0; e < 4; e++) acc[im][in][e] = 0.0f;

    auto load_stage = [&](int buf, int c) {
        const uint32_t sdst = sb + buf * STG_BYTES;
        const size_t kb = (size_t)c * 128 + l_kg * 16;
        #pragma unroll
        for (int p = 0; p < 4; p++) {                       // A: 256 rows
            const int row = l_rb + p * 64;
            const size_t go = (size_t)row * 2048 + kb;
            const uint32_t so = row * 128 + ((l_kg ^ (row & 7)) << 4);
            cpasync16(sdst + STG_AHI + so, a_hi + go);
            cpasync16(sdst + STG_ALO + so, a_lo + go);
        }
        #pragma unroll
        for (int p = 0; p < 2; p++) {                       // B: 128 rows
            const int row = l_rb + p * 64;
            const size_t go = (size_t)row * 2048 + kb;
            const uint32_t so = row * 128 + ((l_kg ^ (row & 7)) << 4);
            cpasync16(sdst + STG_BHI + so, b_hi + go);
            cpasync16(sdst + STG_BLO + so, b_lo + go);
        }
    };

    load_stage(0, 0);  CP_COMMIT();
    load_stage(1, 1);  CP_COMMIT();
    CP_WAIT(1);
    __syncthreads();

    for (int c = 0; c < 16; c++) {
        const int buf = c & 1;
        const uint32_t s0 = sb + buf * STG_BYTES;

        #pragma unroll
        for (int ks = 0; ks < 4; ks++) {
            uint32_t ah[4][4], al[4][4], bh[2][4], bl[2][4];
            const uint32_t asw = ((2 * ks + a_co) ^ a_sw) << 4;
            const uint32_t bsw = ((2 * ks + b_co) ^ b_sw) << 4;
            #pragma unroll
            for (int im = 0; im < 4; im++) {
                const uint32_t ro = (a_row + im * 16) * 128 + asw;
                ldm_x4(ah[im], s0 + STG_AHI + ro);
                ldm_x4(al[im], s0 + STG_ALO + ro);
            }
            #pragma unroll
            for (int j = 0; j < 2; j++) {
                const uint32_t ro = (b_row + j * 16) * 128 + bsw;
                ldm_x4(bh[j], s0 + STG_BHI + ro);
                ldm_x4(bl[j], s0 + STG_BLO + ro);
            }
            #pragma unroll
            for (int im = 0; im < 4; im++)
                #pragma unroll
                for (int in = 0; in < 4; in++) {
                    const uint32_t* ph = &bh[in >> 1][(in & 1) * 2];
                    const uint32_t* pl = &bl[in >> 1][(in & 1) * 2];
                    mma16816(acc[im][in], ah[im], ph);
                    mma16816(acc[im][in], ah[im], pl);
                    mma16816(acc[im][in], al[im], ph);
                }
        }
        __syncthreads();
        if (c + 2 < 16) {
            load_stage(buf, c + 2);
            CP_COMMIT();
            CP_WAIT(1);
        } else {
            CP_WAIT(0);
        }
        __syncthreads();
    }

    // ---- epilogue ----
    const int g = lane >> 2, q = lane & 3;
    #pragma unroll
    for (int im = 0; im < 4; im++) {
        #pragma unroll
        for (int half = 0; half < 2; half++) {
            const int m = m0 + wm + im * 16 + half * 8 + g;
            #pragma unroll
            for (int in = 0; in < 4; in++) {
                const int n = n0 + wn + in * 8 + q * 2;
                const float e0 = acc[im][in][half * 2 + 0];
                const float e1 = acc[im][in][half * 2 + 1];
                if (mode == 1) {
                    *(float2*)(out + (size_t)m * D_ + n) = make_float2(e0, e1);
                } else {
                    const int b = m >> 11, s = m & 2047;
                    const int h = n >> 6, hd = n & 63;
                    const size_t idx = ((size_t)(b * H_ + h) * S_ + s) * HD_ + hd;
                    if (mat == 2) {
                        *(__half2*)(g_vb + idx) = __floats2half2_rn(e0, e1);
                    } else {
                        const float cc = cosT[(size_t)s * HALF_ + (hd >> 1)];
                        const float ss = sinT[(size_t)s * HALF_ + (hd >> 1)];
                        float r0 = e0 * cc - e1 * ss;
                        float r1 = e0 * ss + e1 * cc;
                        if (mat == 0) { r0 *= 0.125f; r1 *= 0.125f; }  // fold 1/sqrt(HD)
                        __nv_bfloat16 h0, h1, l0, l1;
                        split_one(r0, h0, l0);
                        split_one(r1, h1, l1);
                        __nv_bfloat16* hip = (mat == 0) ? g_qhi : g_khi;
                        __nv_bfloat16* lop = (mat == 0) ? g_qlo : g_klo;
                        *(__nv_bfloat162*)(hip + idx) = __nv_bfloat162(h0, h1);
                        *(__nv_bfloat162*)(lop + idx) = __nv_bfloat162(l0, l1);
                    }
                }
            }
        }
    }
}

// ============================================================================
// Flash attention on mma.sync: BQ=128, BKV=64, 8 warps x 16 q-rows, 2 CTA/SM.
// Scores = Qhi.Khi + Qhi.Klo + Qlo.Khi (bf16 3-split, fp32 acc, Q prescaled).
// P,V in fp16 (consistent-l). Epilogue writes bf16 hi/lo splits -> g_ahi/g_alo.
// ============================================================================
#define FQ_HI 0
#define FQ_LO 16384
#define FKV0  32768
#define FSTG  24576
#define FKHI  0
#define FKLO  8192
#define FVV   16384
#define FLASH_SMEM (32768 + 2 * FSTG)   // 80 KB

__global__ __launch_bounds__(256, 2) void flash_mma()
{
    extern __shared__ __align__(1024) char smem[];
    const uint32_t sb = smem_u32(smem);
    const int tid = threadIdx.x, wid = tid >> 5, lane = tid & 31;
    const int qb = (int)gridDim.x - 1 - (int)blockIdx.x;  // heavy blocks first
    const int bh = blockIdx.y;
    const int nc = 2 * qb + 2;
    const int wq0 = wid * 16;

    const char* qh_g = (const char*)g_qhi + ((size_t)bh * S_ + (size_t)qb * 128) * 128;
    const char* ql_g = (const char*)g_qlo + ((size_t)bh * S_ + (size_t)qb * 128) * 128;
    const char* kh_g = (const char*)g_khi + (size_t)bh * S_ * 128;
    const char* kl_g = (const char*)g_klo + (size_t)bh * S_ * 128;
    const char* vv_g = (const char*)g_vb  + (size_t)bh * S_ * 128;

    const int kg = tid & 7;
    #pragma unroll
    for (int p = 0; p < 4; p++) {
        const int row = (tid + p * 256) >> 3;   // 0..127
        const uint32_t so = row * 128 + ((kg ^ (row & 7)) << 4);
        const size_t go = (size_t)row * 128 + kg * 16;
        cpasync16(sb + FQ_HI + so, qh_g + go);
        cpasync16(sb + FQ_LO + so, ql_g + go);
    }
    CP_COMMIT();

    auto load_kv = [&](int st, int c) {
        const uint32_t base = sb + FKV0 + st * FSTG;
        #pragma unroll
        for (int p = 0; p < 2; p++) {
            const int row = (tid + p * 256) >> 3;   // 0..63
            const size_t go = ((size_t)c * 64 + row) * 128 + kg * 16;
            const uint32_t so = row * 128 + ((kg ^ (row & 7)) << 4);
            cpasync16(base + FKHI + so, kh_g + go);
            cpasync16(base + FKLO + so, kl_g + go);
            cpasync16(base + FVV  + so, vv_g + go);
        }
    };
    load_kv(0, 0);  CP_COMMIT();
    load_kv(1, 1);  CP_COMMIT();

    CP_WAIT(2);
    __syncthreads();
    uint32_t qh[4][4], ql[4][4];
    {
        const uint32_t a_row = wq0 + (lane & 15);
        const uint32_t a_co  = lane >> 4;
        #pragma unroll
        for (int ks = 0; ks < 4; ks++) {
            const uint32_t ro = a_row * 128 + (((2 * ks + a_co) ^ (a_row & 7)) << 4);
            ldm_x4(qh[ks], sb + FQ_HI + ro);
            ldm_x4(ql[ks], sb + FQ_LO + ro);
        }
    }

    const int g = lane >> 2, q2 = (lane & 3) * 2;
    float o[8][4];
    #pragma unroll
    for (int j = 0; j < 8; j++)
        #pragma unroll
        for (int e = 0; e < 4; e++) o[j][e] = 0.0f;
    float m0r = -1e30f, m1r = -1e30f, l0r = 0.0f, l1r = 0.0f;

    const uint32_t b_row = (lane & 7) + ((lane >> 4) << 3);
    const uint32_t b_co  = (lane >> 3) & 1;
    const uint32_t v_row = lane & 15;
    const uint32_t v_co  = lane >> 4;

    for (int c = 0; c < nc; c++) {
        const int st = c & 1;
        const uint32_t kbase = sb + FKV0 + st * FSTG;
        CP_WAIT(1);
        __syncthreads();

        // ---- scores: 16 x 64, bf16 3-split ----
        float sc[8][4];
        #pragma unroll
        for (int j = 0; j < 8; j++)
            #pragma unroll
            for (int e = 0; e < 4; e++) sc[j][e] = 0.0f;

        #pragma unroll
        for (int ks = 0; ks < 4; ks++) {
            #pragma unroll
            for (int t = 0; t < 4; t++) {
                uint32_t kh4[4], kl4[4];
                const uint32_t row = b_row + 16 * t;
                const uint32_t ro = row * 128 + (((2 * ks + b_co) ^ (row & 7)) << 4);
                ldm_x4(kh4, kbase + FKHI + ro);
                ldm_x4(kl4, kbase + FKLO + ro);
                mma16816(sc[2 * t],     qh[ks], &kh4[0]);
                mma16816(sc[2 * t],     qh[ks], &kl4[0]);
                mma16816(sc[2 * t],     ql[ks], &kh4[0]);
                mma16816(sc[2 * t + 1], qh[ks], &kh4[2]);
                mma16816(sc[2 * t + 1], qh[ks], &kl4[2]);
                mma16816(sc[2 * t + 1], ql[ks], &kh4[2]);
            }
        }

        // ---- causal mask (diagonal chunks only) ----
        if (c >= 2 * qb) {
            const int kvb = c * 64;
            const int r0 = qb * 128 + wq0 + g, r1 = r0 + 8;
            #pragma unroll
            for (int j = 0; j < 8; j++) {
                const int col = kvb + 8 * j + q2;
                if (col     > r0) sc[j][0] = -1e30f;
                if (col + 1 > r0) sc[j][1] = -1e30f;
                if (col     > r1) sc[j][2] = -1e30f;
                if (col + 1 > r1) sc[j][3] = -1e30f;
            }
        }

        // ---- online softmax ----
        float mx0 = -1e30f, mx1 = -1e30f;
        #pragma unroll
        for (int j = 0; j < 8; j++) {
            mx0 = fmaxf(mx0, fmaxf(sc[j][0], sc[j][1]));
            mx1 = fmaxf(mx1, fmaxf(sc[j][2], sc[j][3]));
        }
        mx0 = fmaxf(mx0, __shfl_xor_sync(0xffffffffu, mx0, 1));
        mx0 = fmaxf(mx0, __shfl_xor_sync(0xffffffffu, mx0, 2));
        mx1 = fmaxf(mx1, __shfl_xor_sync(0xffffffffu, mx1, 1));
        mx1 = fmaxf(mx1, __shfl_xor_sync(0xffffffffu, mx1, 2));
        const float mn0 = fmaxf(m0r, mx0), mn1 = fmaxf(m1r, mx1);
        const float al0 = __expf(m0r - mn0), al1 = __expf(m1r - mn1);

        uint32_t pa[8][2];
        float rs0 = 0.0f, rs1 = 0.0f;
        #pragma unroll
        for (int j = 0; j < 8; j++) {
            const float p0 = __expf(sc[j][0] - mn0);
            const float p1 = __expf(sc[j][1] - mn0);
            const float p2 = __expf(sc[j][2] - mn1);
            const float p3 = __expf(sc[j][3] - mn1);
            __half2 h01 = __floats2half2_rn(p0, p1);
            __half2 h23 = __floats2half2_rn(p2, p3);
            pa[j][0] = *(uint32_t*)&h01;
            pa[j][1] = *(uint32_t*)&h23;
            rs0 += __low2float(h01) + __high2float(h01);
            rs1 += __low2float(h23) + __high2float(h23);
        }
        rs0 += __shfl_xor_sync(0xffffffffu, rs0, 1);
        rs0 += __shfl_xor_sync(0xffffffffu, rs0, 2);
        rs1 += __shfl_xor_sync(0xffffffffu, rs1, 1);
        rs1 += __shfl_xor_sync(0xffffffffu, rs1, 2);
        l0r = l0r * al0 + rs0;
        l1r = l1r * al1 + rs1;
        m0r = mn0; m1r = mn1;
        #pragma unroll
        for (int j = 0; j < 8; j++) {
            o[j][0] *= al0; o[j][1] *= al0;
            o[j][2] *= al1; o[j][3] *= al1;
        }

        // ---- PV: P (fp16 regs) x V^T (fp16, ldmatrix.trans) ----
        #pragma unroll
        for (int t = 0; t < 4; t++) {
            const uint32_t pA[4] = { pa[2*t][0], pa[2*t][1], pa[2*t+1][0], pa[2*t+1][1] };
            const uint32_t row = v_row + 16 * t;
            #pragma unroll
            for (int u = 0; u < 4; u++) {
                uint32_t vt[4];
                const uint32_t ro = row * 128 + (((2 * u + v_co) ^ (row & 7)) << 4);
                ldm_x4_t(vt, kbase + FVV + ro);
                mma16816h(o[2 * u],     pA, &vt[0]);
                mma16816h(o[2 * u + 1], pA, &vt[2]);
            }
        }

        __syncthreads();
        if (c + 2 < nc) load_kv(st, c + 2);
        CP_COMMIT();
    }

    // ---- epilogue: write bf16 hi/lo splits directly -> g_ahi/g_alo [B,S,D] ----
    const int b = bh >> 4, h = bh & 15;
    const float i0 = 1.0f / l0r, i1 = 1.0f / l1r;
    const int s0 = qb * 128 + wq0 + g, s1 = s0 + 8;
    const size_t r0 = ((size_t)b * S_ + s0) * D_ + h * HD_;
    const size_t r1 = ((size_t)b * S_ + s1) * D_ + h * HD_;
    #pragma unroll
    for (int j = 0; j < 8; j++) {
        const int col = 8 * j + q2;
        __nv_bfloat16 h0, h1, l0, l1;
        split_one(o[j][0] * i0, h0, l0);
        split_one(o[j][1] * i0, h1, l1);
        *(__nv_bfloat162*)(g_ahi + r0 + col) = __nv_bfloat162(h0, h1);
        *(__nv_bfloat162*)(g_alo + r0 + col) = __nv_bfloat162(l0, l1);
        split_one(o[j][2] * i1, h0, l0);
        split_one(o[j][3] * i1, h1, l1);
        *(__nv_bfloat162*)(g_ahi + r1 + col) = __nv_bfloat162(h0, h1);
        *(__nv_bfloat162*)(g_alo + r1 + col) = __nv_bfloat162(l0, l1);
    }
}

// ============================================================================
extern "C" void kernel_launch(void* const* d_in, const int* in_sizes, int n_in,
                              void* d_out, int out_size)
{
    (void)in_sizes; (void)n_in; (void)out_size;
    const float* x    = (const float*)d_in[0];
    const float* fcos = (const float*)d_in[1];
    const float* fsin = (const float*)d_in[2];
    const float* wq   = (const float*)d_in[3];
    const float* wk   = (const float*)d_in[4];
    const float* wv   = (const float*)d_in[5];
    const float* wo   = (const float*)d_in[6];
    float* out = (float*)d_out;

    __nv_bfloat16 *p_ahi, *p_alo;
    cudaGetSymbolAddress((void**)&p_ahi, g_ahi);
    cudaGetSymbolAddress((void**)&p_alo, g_alo);
    cudaFuncSetAttribute(gemm_tc,
                         cudaFuncAttributeMaxDynamicSharedMemorySize, GEMM_SMEM);
    cudaFuncSetAttribute(flash_mma,
                         cudaFuncAttributeMaxDynamicSharedMemorySize, FLASH_SMEM);

    const int n4x = M_ * D_ / 4;
    const int n4w = D_ * D_ / 4;

    // 0) fp32 -> bf16 hi/lo splits (x + all 4 weights)
    split_kernel<<<n4x / 256, 256>>>(x, p_ahi, p_alo, n4x);
    split4_kernel<<<dim3(n4w / 256, 4), 256>>>(wq, wk, wv, wo, n4w);

    // 1) QKV projections + RoPE -> attention operands (bf16 splits + fp16 V)
    gemm_tc<<<dim3(M_ / 256, 24), 512, GEMM_SMEM>>>(p_ahi, p_alo, fcos, fsin, out, 0);

    // 2) causal flash attention (tensor cores) -> bf16 splits in g_ahi/g_alo
    flash_mma<<<dim3(S_ / 128, B_ * H_), 256, FLASH_SMEM>>>();

    // 3) output projection -> d_out
    gemm_tc<<<dim3(M_ / 256, 8), 512, GEMM_SMEM>>>(p_ahi, p_alo, fcos, fsin, out, 1);
}

// round 12
// speedup vs baseline: 4.1397x; 1.2451x over previous
#include <cuda_runtime.h>
#include <cuda_bf16.h>
#include <cuda_fp16.h>
#include <cstdint>
#include <cstddef>

#define B_    4
#define S_    2048
#define D_    1024
#define H_    16
#define HD_   64
#define HALF_ 32
#define M_    (B_ * S_)   // 8192

// ---------------- scratch (allocation-free) ----------------
// GEMM A operand (x, then attn-out), fp16 hi/lo
__device__ __align__(16) __half g_ahi[M_ * D_];
__device__ __align__(16) __half g_alo[M_ * D_];
// weights q,k,v,o packed, fp16 hi/lo
__device__ __align__(16) __half g_whi[4 * D_ * D_];
__device__ __align__(16) __half g_wlo[4 * D_ * D_];
// attention operands, [B,H,S,HD] (Q pre-scaled by 1/8, RoPE applied)
__device__ __align__(16) __nv_bfloat16 g_qhi[M_ * D_];
__device__ __align__(16) __nv_bfloat16 g_qlo[M_ * D_];
__device__ __align__(16) __nv_bfloat16 g_khi[M_ * D_];
__device__ __align__(16) __nv_bfloat16 g_klo[M_ * D_];
__device__ __align__(16) __half        g_vb [M_ * D_];    // V in fp16

// ---------------- helpers (sm_80+ portable PTX only) ----------------
__device__ __forceinline__ uint32_t smem_u32(const void* p) {
    uint32_t a;
    asm("{ .reg .u64 t; cvta.to.shared.u64 t, %1; cvt.u32.u64 %0, t; }" : "=r"(a) : "l"(p));
    return a;
}
__device__ __forceinline__ void cpasync16(uint32_t dst, const void* src) {
    asm volatile("cp.async.cg.shared.global [%0], [%1], 16;" :: "r"(dst), "l"(src));
}
__device__ __forceinline__ void ldm_x4(uint32_t* r, uint32_t a) {
    asm volatile("ldmatrix.sync.aligned.m8n8.x4.shared.b16 {%0,%1,%2,%3}, [%4];"
        : "=r"(r[0]), "=r"(r[1]), "=r"(r[2]), "=r"(r[3]) : "r"(a));
}
__device__ __forceinline__ void ldm_x4_t(uint32_t* r, uint32_t a) {
    asm volatile("ldmatrix.sync.aligned.m8n8.x4.trans.shared.b16 {%0,%1,%2,%3}, [%4];"
        : "=r"(r[0]), "=r"(r[1]), "=r"(r[2]), "=r"(r[3]) : "r"(a));
}
__device__ __forceinline__ void mma16816(float* d, const uint32_t* a, const uint32_t* b) {
    asm volatile("mma.sync.aligned.m16n8k16.row.col.f32.bf16.bf16.f32 "
        "{%0,%1,%2,%3}, {%4,%5,%6,%7}, {%8,%9}, {%0,%1,%2,%3};"
        : "+f"(d[0]), "+f"(d[1]), "+f"(d[2]), "+f"(d[3])
        : "r"(a[0]), "r"(a[1]), "r"(a[2]), "r"(a[3]), "r"(b[0]), "r"(b[1]));
}
__device__ __forceinline__ void mma16816h(float* d, const uint32_t* a, const uint32_t* b) {
    asm volatile("mma.sync.aligned.m16n8k16.row.col.f32.f16.f16.f32 "
        "{%0,%1,%2,%3}, {%4,%5,%6,%7}, {%8,%9}, {%0,%1,%2,%3};"
        : "+f"(d[0]), "+f"(d[1]), "+f"(d[2]), "+f"(d[3])
        : "r"(a[0]), "r"(a[1]), "r"(a[2]), "r"(a[3]), "r"(b[0]), "r"(b[1]));
}
#define CP_COMMIT() asm volatile("cp.async.commit_group;" ::: "memory")
#define CP_WAIT(n)  asm volatile("cp.async.wait_group %0;" :: "n"(n) : "memory")

__device__ __forceinline__ void split_bf(float v, __nv_bfloat16& h, __nv_bfloat16& l) {
    h = __float2bfloat16(v);
    l = __float2bfloat16(v - __bfloat162float(h));
}
__device__ __forceinline__ void split_fp16(float v, __half& h, __half& l) {
    h = __float2half(v);
    l = __float2half(v - __half2float(h));
}

// ============================================================================
// split: fp32 -> (fp16 hi, fp16 lo)
// ============================================================================
__global__ __launch_bounds__(256) void split_kernel(
    const float* __restrict__ src, __half* __restrict__ hi,
    __half* __restrict__ lo, int n4)
{
    int i = blockIdx.x * 256 + threadIdx.x;
    if (i >= n4) return;
    float4 v = ((const float4*)src)[i];
    __half h0, h1, h2, h3, l0, l1, l2, l3;
    split_fp16(v.x, h0, l0); split_fp16(v.y, h1, l1);
    split_fp16(v.z, h2, l2); split_fp16(v.w, h3, l3);
    ((__half2*)hi)[2 * i]     = __half2(h0, h1);
    ((__half2*)hi)[2 * i + 1] = __half2(h2, h3);
    ((__half2*)lo)[2 * i]     = __half2(l0, l1);
    ((__half2*)lo)[2 * i + 1] = __half2(l2, l3);
}

// all 4 weights in one launch (grid.y selects matrix)
__global__ __launch_bounds__(256) void split4_kernel(
    const float* __restrict__ w0, const float* __restrict__ w1,
    const float* __restrict__ w2, const float* __restrict__ w3, int n4)
{
    const int m = blockIdx.y;
    const float* src = (m == 0) ? w0 : (m == 1) ? w1 : (m == 2) ? w2 : w3;
    __half* hi = g_whi + (size_t)m * D_ * D_;
    __half* lo = g_wlo + (size_t)m * D_ * D_;
    int i = blockIdx.x * 256 + threadIdx.x;
    if (i >= n4) return;
    float4 v = ((const float4*)src)[i];
    __half h0, h1, h2, h3, l0, l1, l2, l3;
    split_fp16(v.x, h0, l0); split_fp16(v.y, h1, l1);
    split_fp16(v.z, h2, l2); split_fp16(v.w, h3, l3);
    ((__half2*)hi)[2 * i]     = __half2(h0, h1);
    ((__half2*)hi)[2 * i + 1] = __half2(h2, h3);
    ((__half2*)lo)[2 * i]     = __half2(l0, l1);
    ((__half2*)lo)[2 * i + 1] = __half2(l2, l3);
}

// ============================================================================
// mma.sync fp16 2-term GEMM: C = Ah*(Bh + Bl)  (A-lo term dropped, ~1.4e-4 rel).
// Tile 256x128, BK=64, 512 thr (16 warps = 4m x 4n), warp tile 64x32,
// double-buffered cp.async, 128KB smem.
// mode 0: A = x(hi), W = wq/wk/wv; RoPE epilogue -> bf16 q/k splits, fp16 v
// mode 1: A = attn-out(hi) [written by flash], W = wo; plain -> out
// ============================================================================
#define STG_AH 0
#define STG_BH 32768
#define STG_BL 49152
#define STG_BYTES 65536
#define GEMM_SMEM (2 * STG_BYTES)   // 128 KB

__global__ __launch_bounds__(512, 1) void gemm_tc(
    const __half* __restrict__ Ahi_g,
    const float* __restrict__ cosT, const float* __restrict__ sinT,
    float* __restrict__ out, int mode)
{
    extern __shared__ __align__(1024) char smem[];
    const uint32_t sb = smem_u32(smem);
    const int tid = threadIdx.x;
    const int wid = tid >> 5, lane = tid & 31;
    const int m0 = blockIdx.x * 256;
    const int by = blockIdx.y;

    int mat, n0;
    if (mode == 0) { mat = by >> 3; n0 = (by & 7) * 128; }
    else           { mat = 3;       n0 = by * 128; }
    const char* a_hi = (const char*)(Ahi_g + (size_t)m0 * D_);
    const char* b_hi = (const char*)(g_whi + (size_t)mat * D_ * D_ + (size_t)n0 * D_);
    const char* b_lo = (const char*)(g_wlo + (size_t)mat * D_ * D_ + (size_t)n0 * D_);

    const int l_kg = tid & 7;
    const int l_rb = tid >> 3;            // 0..63

    const int wm = (wid & 3) * 64;
    const int wn = (wid >> 2) * 32;
    const uint32_t a_row = wm + (lane & 15);
    const uint32_t a_co  = lane >> 4;
    const uint32_t a_sw  = a_row & 7;
    const uint32_t b_row = wn + (lane & 7) + ((lane >> 4) << 3);
    const uint32_t b_co  = (lane >> 3) & 1;
    const uint32_t b_sw  = b_row & 7;

    float acc[4][4][4];
    #pragma unroll
    for (int im = 0; im < 4; im++)
        #pragma unroll
        for (int in = 0; in < 4; in++)
            #pragma unroll
            for (int e = 0; e < 4; e++) acc[im][in][e] = 0.0f;

    auto load_stage = [&](int buf, int c) {
        const uint32_t sdst = sb + buf * STG_BYTES;
        const size_t kb = (size_t)c * 128 + l_kg * 16;
        #pragma unroll
        for (int p = 0; p < 4; p++) {                       // A-hi: 256 rows
            const int row = l_rb + p * 64;
            const size_t go = (size_t)row * 2048 + kb;
            const uint32_t so = row * 128 + ((l_kg ^ (row & 7)) << 4);
            cpasync16(sdst + STG_AH + so, a_hi + go);
        }
        #pragma unroll
        for (int p = 0; p < 2; p++) {                       // B hi+lo: 128 rows
            const int row = l_rb + p * 64;
            const size_t go = (size_t)row * 2048 + kb;
            const uint32_t so = row * 128 + ((l_kg ^ (row & 7)) << 4);
            cpasync16(sdst + STG_BH + so, b_hi + go);
            cpasync16(sdst + STG_BL + so, b_lo + go);
        }
    };

    load_stage(0, 0);  CP_COMMIT();
    load_stage(1, 1);  CP_COMMIT();
    CP_WAIT(1);
    __syncthreads();

    for (int c = 0; c < 16; c++) {
        const int buf = c & 1;
        const uint32_t s0 = sb + buf * STG_BYTES;

        #pragma unroll
        for (int ks = 0; ks < 4; ks++) {
            uint32_t ah[4][4], bh[2][4], bl[2][4];
            const uint32_t asw = ((2 * ks + a_co) ^ a_sw) << 4;
            const uint32_t bsw = ((2 * ks + b_co) ^ b_sw) << 4;
            #pragma unroll
            for (int im = 0; im < 4; im++)
                ldm_x4(ah[im], s0 + STG_AH + (a_row + im * 16) * 128 + asw);
            #pragma unroll
            for (int j = 0; j < 2; j++) {
                const uint32_t ro = (b_row + j * 16) * 128 + bsw;
                ldm_x4(bh[j], s0 + STG_BH + ro);
                ldm_x4(bl[j], s0 + STG_BL + ro);
            }
            #pragma unroll
            for (int im = 0; im < 4; im++)
                #pragma unroll
                for (int in = 0; in < 4; in++) {
                    mma16816h(acc[im][in], ah[im], &bh[in >> 1][(in & 1) * 2]);
                    mma16816h(acc[im][in], ah[im], &bl[in >> 1][(in & 1) * 2]);
                }
        }
        __syncthreads();
        if (c + 2 < 16) {
            load_stage(buf, c + 2);
            CP_COMMIT();
            CP_WAIT(1);
        } else {
            CP_WAIT(0);
        }
        __syncthreads();
    }

    // ---- epilogue ----
    const int g = lane >> 2, q = lane & 3;
    #pragma unroll
    for (int im = 0; im < 4; im++) {
        #pragma unroll
        for (int half = 0; half < 2; half++) {
            const int m = m0 + wm + im * 16 + half * 8 + g;
            #pragma unroll
            for (int in = 0; in < 4; in++) {
                const int n = n0 + wn + in * 8 + q * 2;
                const float e0 = acc[im][in][half * 2 + 0];
                const float e1 = acc[im][in][half * 2 + 1];
                if (mode == 1) {
                    *(float2*)(out + (size_t)m * D_ + n) = make_float2(e0, e1);
                } else {
                    const int b = m >> 11, s = m & 2047;
                    const int h = n >> 6, hd = n & 63;
                    const size_t idx = ((size_t)(b * H_ + h) * S_ + s) * HD_ + hd;
                    if (mat == 2) {
                        *(__half2*)(g_vb + idx) = __floats2half2_rn(e0, e1);
                    } else {
                        const float cc = cosT[(size_t)s * HALF_ + (hd >> 1)];
                        const float ss = sinT[(size_t)s * HALF_ + (hd >> 1)];
                        float r0 = e0 * cc - e1 * ss;
                        float r1 = e0 * ss + e1 * cc;
                        if (mat == 0) { r0 *= 0.125f; r1 *= 0.125f; }  // fold 1/sqrt(HD)
                        __nv_bfloat16 h0, h1, l0, l1;
                        split_bf(r0, h0, l0);
                        split_bf(r1, h1, l1);
                        __nv_bfloat16* hip = (mat == 0) ? g_qhi : g_khi;
                        __nv_bfloat16* lop = (mat == 0) ? g_qlo : g_klo;
                        *(__nv_bfloat162*)(hip + idx) = __nv_bfloat162(h0, h1);
                        *(__nv_bfloat162*)(lop + idx) = __nv_bfloat162(l0, l1);
                    }
                }
            }
        }
    }
}

// ============================================================================
// Flash attention on mma.sync: BQ=128, BKV=64, 8 warps x 16 q-rows, 2 CTA/SM.
// Scores = Qhi.Khi + Qhi.Klo + Qlo.Khi (bf16 3-split, fp32 acc, Q prescaled).
// P,V in fp16 (consistent-l). Epilogue writes fp16 hi/lo splits -> g_ahi/g_alo.
// ============================================================================
#define FQ_HI 0
#define FQ_LO 16384
#define FKV0  32768
#define FSTG  24576
#define FKHI  0
#define FKLO  8192
#define FVV   16384
#define FLASH_SMEM (32768 + 2 * FSTG)   // 80 KB

__global__ __launch_bounds__(256, 2) void flash_mma()
{
    extern __shared__ __align__(1024) char smem[];
    const uint32_t sb = smem_u32(smem);
    const int tid = threadIdx.x, wid = tid >> 5, lane = tid & 31;
    const int qb = (int)gridDim.x - 1 - (int)blockIdx.x;  // heavy blocks first
    const int bh = blockIdx.y;
    const int nc = 2 * qb + 2;
    const int wq0 = wid * 16;

    const char* qh_g = (const char*)g_qhi + ((size_t)bh * S_ + (size_t)qb * 128) * 128;
    const char* ql_g = (const char*)g_qlo + ((size_t)bh * S_ + (size_t)qb * 128) * 128;
    const char* kh_g = (const char*)g_khi + (size_t)bh * S_ * 128;
    const char* kl_g = (const char*)g_klo + (size_t)bh * S_ * 128;
    const char* vv_g = (const char*)g_vb  + (size_t)bh * S_ * 128;

    const int kg = tid & 7;
    #pragma unroll
    for (int p = 0; p < 4; p++) {
        const int row = (tid + p * 256) >> 3;   // 0..127
        const uint32_t so = row * 128 + ((kg ^ (row & 7)) << 4);
        const size_t go = (size_t)row * 128 + kg * 16;
        cpasync16(sb + FQ_HI + so, qh_g + go);
        cpasync16(sb + FQ_LO + so, ql_g + go);
    }
    CP_COMMIT();

    auto load_kv = [&](int st, int c) {
        const uint32_t base = sb + FKV0 + st * FSTG;
        #pragma unroll
        for (int p = 0; p < 2; p++) {
            const int row = (tid + p * 256) >> 3;   // 0..63
            const size_t go = ((size_t)c * 64 + row) * 128 + kg * 16;
            const uint32_t so = row * 128 + ((kg ^ (row & 7)) << 4);
            cpasync16(base + FKHI + so, kh_g + go);
            cpasync16(base + FKLO + so, kl_g + go);
            cpasync16(base + FVV  + so, vv_g + go);
        }
    };
    load_kv(0, 0);  CP_COMMIT();
    load_kv(1, 1);  CP_COMMIT();

    CP_WAIT(2);
    __syncthreads();
    uint32_t qh[4][4], ql[4][4];
    {
        const uint32_t a_row = wq0 + (lane & 15);
        const uint32_t a_co  = lane >> 4;
        #pragma unroll
        for (int ks = 0; ks < 4; ks++) {
            const uint32_t ro = a_row * 128 + (((2 * ks + a_co) ^ (a_row & 7)) << 4);
            ldm_x4(qh[ks], sb + FQ_HI + ro);
            ldm_x4(ql[ks], sb + FQ_LO + ro);
        }
    }

    const int g = lane >> 2, q2 = (lane & 3) * 2;
    float o[8][4];
    #pragma unroll
    for (int j = 0; j < 8; j++)
        #pragma unroll
        for (int e = 0; e < 4; e++) o[j][e] = 0.0f;
    float m0r = -1e30f, m1r = -1e30f, l0r = 0.0f, l1r = 0.0f;

    const uint32_t b_row = (lane & 7) + ((lane >> 4) << 3);
    const uint32_t b_co  = (lane >> 3) & 1;
    const uint32_t v_row = lane & 15;
    const uint32_t v_co  = lane >> 4;

    for (int c = 0; c < nc; c++) {
        const int st = c & 1;
        const uint32_t kbase = sb + FKV0 + st * FSTG;
        CP_WAIT(1);
        __syncthreads();

        // ---- scores: 16 x 64, bf16 3-split ----
        float sc[8][4];
        #pragma unroll
        for (int j = 0; j < 8; j++)
            #pragma unroll
            for (int e = 0; e < 4; e++) sc[j][e] = 0.0f;

        #pragma unroll
        for (int ks = 0; ks < 4; ks++) {
            #pragma unroll
            for (int t = 0; t < 4; t++) {
                uint32_t kh4[4], kl4[4];
                const uint32_t row = b_row + 16 * t;
                const uint32_t ro = row * 128 + (((2 * ks + b_co) ^ (row & 7)) << 4);
                ldm_x4(kh4, kbase + FKHI + ro);
                ldm_x4(kl4, kbase + FKLO + ro);
                mma16816(sc[2 * t],     qh[ks], &kh4[0]);
                mma16816(sc[2 * t],     qh[ks], &kl4[0]);
                mma16816(sc[2 * t],     ql[ks], &kh4[0]);
                mma16816(sc[2 * t + 1], qh[ks], &kh4[2]);
                mma16816(sc[2 * t + 1], qh[ks], &kl4[2]);
                mma16816(sc[2 * t + 1], ql[ks], &kh4[2]);
            }
        }

        // ---- causal mask (diagonal chunks only) ----
        if (c >= 2 * qb) {
            const int kvb = c * 64;
            const int r0 = qb * 128 + wq0 + g, r1 = r0 + 8;
            #pragma unroll
            for (int j = 0; j < 8; j++) {
                const int col = kvb + 8 * j + q2;
                if (col     > r0) sc[j][0] = -1e30f;
                if (col + 1 > r0) sc[j][1] = -1e30f;
                if (col     > r1) sc[j][2] = -1e30f;
                if (col + 1 > r1) sc[j][3] = -1e30f;
            }
        }

        // ---- online softmax ----
        float mx0 = -1e30f, mx1 = -1e30f;
        #pragma unroll
        for (int j = 0; j < 8; j++) {
            mx0 = fmaxf(mx0, fmaxf(sc[j][0], sc[j][1]));
            mx1 = fmaxf(mx1, fmaxf(sc[j][2], sc[j][3]));
        }
        mx0 = fmaxf(mx0, __shfl_xor_sync(0xffffffffu, mx0, 1));
        mx0 = fmaxf(mx0, __shfl_xor_sync(0xffffffffu, mx0, 2));
        mx1 = fmaxf(mx1, __shfl_xor_sync(0xffffffffu, mx1, 1));
        mx1 = fmaxf(mx1, __shfl_xor_sync(0xffffffffu, mx1, 2));
        const float mn0 = fmaxf(m0r, mx0), mn1 = fmaxf(m1r, mx1);
        const float al0 = __expf(m0r - mn0), al1 = __expf(m1r - mn1);

        uint32_t pa[8][2];
        float rs0 = 0.0f, rs1 = 0.0f;
        #pragma unroll
        for (int j = 0; j < 8; j++) {
            const float p0 = __expf(sc[j][0] - mn0);
            const float p1 = __expf(sc[j][1] - mn0);
            const float p2 = __expf(sc[j][2] - mn1);
            const float p3 = __expf(sc[j][3] - mn1);
            __half2 h01 = __floats2half2_rn(p0, p1);
            __half2 h23 = __floats2half2_rn(p2, p3);
            pa[j][0] = *(uint32_t*)&h01;
            pa[j][1] = *(uint32_t*)&h23;
            rs0 += __low2float(h01) + __high2float(h01);
            rs1 += __low2float(h23) + __high2float(h23);
        }
        rs0 += __shfl_xor_sync(0xffffffffu, rs0, 1);
        rs0 += __shfl_xor_sync(0xffffffffu, rs0, 2);
        rs1 += __shfl_xor_sync(0xffffffffu, rs1, 1);
        rs1 += __shfl_xor_sync(0xffffffffu, rs1, 2);
        l0r = l0r * al0 + rs0;
        l1r = l1r * al1 + rs1;
        m0r = mn0; m1r = mn1;
        #pragma unroll
        for (int j = 0; j < 8; j++) {
            o[j][0] *= al0; o[j][1] *= al0;
            o[j][2] *= al1; o[j][3] *= al1;
        }

        // ---- PV: P (fp16 regs) x V^T (fp16, ldmatrix.trans) ----
        #pragma unroll
        for (int t = 0; t < 4; t++) {
            const uint32_t pA[4] = { pa[2*t][0], pa[2*t][1], pa[2*t+1][0], pa[2*t+1][1] };
            const uint32_t row = v_row + 16 * t;
            #pragma unroll
            for (int u = 0; u < 4; u++) {
                uint32_t vt[4];
                const uint32_t ro = row * 128 + (((2 * u + v_co) ^ (row & 7)) << 4);
                ldm_x4_t(vt, kbase + FVV + ro);
                mma16816h(o[2 * u],     pA, &vt[0]);
                mma16816h(o[2 * u + 1], pA, &vt[2]);
            }
        }

        __syncthreads();
        if (c + 2 < nc) load_kv(st, c + 2);
        CP_COMMIT();
    }

    // ---- epilogue: write fp16 hi/lo splits -> g_ahi/g_alo [B,S,D] ----
    const int b = bh >> 4, h = bh & 15;
    const float i0 = 1.0f / l0r, i1 = 1.0f / l1r;
    const int s0 = qb * 128 + wq0 + g, s1 = s0 + 8;
    const size_t r0 = ((size_t)b * S_ + s0) * D_ + h * HD_;
    const size_t r1 = ((size_t)b * S_ + s1) * D_ + h * HD_;
    #pragma unroll
    for (int j = 0; j < 8; j++) {
        const int col = 8 * j + q2;
        __half h0, h1, l0, l1;
        split_fp16(o[j][0] * i0, h0, l0);
        split_fp16(o[j][1] * i0, h1, l1);
        *(__half2*)(g_ahi + r0 + col) = __half2(h0, h1);
        *(__half2*)(g_alo + r0 + col) = __half2(l0, l1);
        split_fp16(o[j][2] * i1, h0, l0);
        split_fp16(o[j][3] * i1, h1, l1);
        *(__half2*)(g_ahi + r1 + col) = __half2(h0, h1);
        *(__half2*)(g_alo + r1 + col) = __half2(l0, l1);
    }
}

// ============================================================================
extern "C" void kernel_launch(void* const* d_in, const int* in_sizes, int n_in,
                              void* d_out, int out_size)
{
    (void)in_sizes; (void)n_in; (void)out_size;
    const float* x    = (const float*)d_in[0];
    const float* fcos = (const float*)d_in[1];
    const float* fsin = (const float*)d_in[2];
    const float* wq   = (const float*)d_in[3];
    const float* wk   = (const float*)d_in[4];
    const float* wv   = (const float*)d_in[5];
    const float* wo   = (const float*)d_in[6];
    float* out = (float*)d_out;

    __half *p_ahi, *p_alo;
    cudaGetSymbolAddress((void**)&p_ahi, g_ahi);
    cudaGetSymbolAddress((void**)&p_alo, g_alo);
    cudaFuncSetAttribute(gemm_tc,
                         cudaFuncAttributeMaxDynamicSharedMemorySize, GEMM_SMEM);
    cudaFuncSetAttribute(flash_mma,
                         cudaFuncAttributeMaxDynamicSharedMemorySize, FLASH_SMEM);

    const int n4x = M_ * D_ / 4;
    const int n4w = D_ * D_ / 4;

    // 0) fp32 -> fp16 hi/lo splits (x + all 4 weights)
    split_kernel<<<n4x / 256, 256>>>(x, p_ahi, p_alo, n4x);
    split4_kernel<<<dim3(n4w / 256, 4), 256>>>(wq, wk, wv, wo, n4w);

    // 1) QKV projections + RoPE -> attention operands (bf16 q/k splits + fp16 V)
    gemm_tc<<<dim3(M_ / 256, 24), 512, GEMM_SMEM>>>(p_ahi, fcos, fsin, out, 0);

    // 2) causal flash attention (tensor cores) -> fp16 splits in g_ahi/g_alo
    flash_mma<<<dim3(S_ / 128, B_ * H_), 256, FLASH_SMEM>>>();

    // 3) output projection -> d_out
    gemm_tc<<<dim3(M_ / 256, 8), 512, GEMM_SMEM>>>(p_ahi, fcos, fsin, out, 1);
}

// round 15
// speedup vs baseline: 4.6783x; 1.1301x over previous
#include <cuda_runtime.h>
#include <cuda_bf16.h>
#include <cuda_fp16.h>
#include <cstdint>
#include <cstddef>

#define B_    4
#define S_    2048
#define D_    1024
#define H_    16
#define HD_   64
#define HALF_ 32
#define M_    (B_ * S_)   // 8192

// ---------------- scratch (allocation-free) ----------------
__device__ __align__(16) __half g_ah [M_ * D_];        // GEMM A operand (fp16)
__device__ __align__(16) __half g_whi[4 * D_ * D_];    // weights hi
__device__ __align__(16) __half g_wlo[4 * D_ * D_];    // weights lo
// attention operands, [B,H,S,HD] (Q pre-scaled by 1/8, RoPE applied)
__device__ __align__(16) __half g_qh[M_ * D_];
__device__ __align__(16) __half g_ql[M_ * D_];
__device__ __align__(16) __half g_kh[M_ * D_];
__device__ __align__(16) __half g_vb[M_ * D_];

// ---------------- helpers (sm_80+ portable PTX only) ----------------
__device__ __forceinline__ uint32_t smem_u32(const void* p) {
    uint32_t a;
    asm("{ .reg .u64 t; cvta.to.shared.u64 t, %1; cvt.u32.u64 %0, t; }" : "=r"(a) : "l"(p));
    return a;
}
__device__ __forceinline__ void cpasync16(uint32_t dst, const void* src) {
    asm volatile("cp.async.cg.shared.global [%0], [%1], 16;" :: "r"(dst), "l"(src));
}
__device__ __forceinline__ void ldm_x4(uint32_t* r, uint32_t a) {
    asm volatile("ldmatrix.sync.aligned.m8n8.x4.shared.b16 {%0,%1,%2,%3}, [%4];"
        : "=r"(r[0]), "=r"(r[1]), "=r"(r[2]), "=r"(r[3]) : "r"(a));
}
__device__ __forceinline__ void ldm_x4_t(uint32_t* r, uint32_t a) {
    asm volatile("ldmatrix.sync.aligned.m8n8.x4.trans.shared.b16 {%0,%1,%2,%3}, [%4];"
        : "=r"(r[0]), "=r"(r[1]), "=r"(r[2]), "=r"(r[3]) : "r"(a));
}
__device__ __forceinline__ void mma16816h(float* d, const uint32_t* a, const uint32_t* b) {
    asm volatile("mma.sync.aligned.m16n8k16.row.col.f32.f16.f16.f32 "
        "{%0,%1,%2,%3}, {%4,%5,%6,%7}, {%8,%9}, {%0,%1,%2,%3};"
        : "+f"(d[0]), "+f"(d[1]), "+f"(d[2]), "+f"(d[3])
        : "r"(a[0]), "r"(a[1]), "r"(a[2]), "r"(a[3]), "r"(b[0]), "r"(b[1]));
}
#define CP_COMMIT() asm volatile("cp.async.commit_group;" ::: "memory")
#define CP_WAIT(n)  asm volatile("cp.async.wait_group %0;" :: "n"(n) : "memory")

__device__ __forceinline__ void split_fp16(float v, __half& h, __half& l) {
    h = __float2half(v);
    l = __float2half(v - __half2float(h));
}

// ============================================================================
// convert: fp32 -> fp16
// ============================================================================
__global__ __launch_bounds__(256) void convert_kernel(
    const float* __restrict__ src, __half* __restrict__ dst, int n4)
{
    int i = blockIdx.x * 256 + threadIdx.x;
    if (i >= n4) return;
    float4 v = ((const float4*)src)[i];
    ((__half2*)dst)[2 * i]     = __floats2half2_rn(v.x, v.y);
    ((__half2*)dst)[2 * i + 1] = __floats2half2_rn(v.z, v.w);
}

// all 4 weights, fp16 hi/lo (grid.y selects matrix)
__global__ __launch_bounds__(256) void split4_kernel(
    const float* __restrict__ w0, const float* __restrict__ w1,
    const float* __restrict__ w2, const float* __restrict__ w3, int n4)
{
    const int m = blockIdx.y;
    const float* src = (m == 0) ? w0 : (m == 1) ? w1 : (m == 2) ? w2 : w3;
    __half* hi = g_whi + (size_t)m * D_ * D_;
    __half* lo = g_wlo + (size_t)m * D_ * D_;
    int i = blockIdx.x * 256 + threadIdx.x;
    if (i >= n4) return;
    float4 v = ((const float4*)src)[i];
    __half h0, h1, h2, h3, l0, l1, l2, l3;
    split_fp16(v.x, h0, l0); split_fp16(v.y, h1, l1);
    split_fp16(v.z, h2, l2); split_fp16(v.w, h3, l3);
    ((__half2*)hi)[2 * i]     = __half2(h0, h1);
    ((__half2*)hi)[2 * i + 1] = __half2(h2, h3);
    ((__half2*)lo)[2 * i]     = __half2(l0, l1);
    ((__half2*)lo)[2 * i + 1] = __half2(l2, l3);
}

// ============================================================================
// mma.sync fp16 2-term GEMM: C = Ah*(Bh + Bl). Tile 256x128, BK=64, 512 thr,
// warp tile 64x32, 3-stage cp.async pipeline (one sync/chunk), 192KB smem.
// mode 0: A = fp16(x), W = wq/wk/wv; RoPE epilogue -> q (fp16 hi/lo), k, v
// mode 1: A = attn-out (fp16), W = wo; plain -> out
// ============================================================================
#define STG_AH 0
#define STG_BH 32768
#define STG_BL 49152
#define STG_BYTES 65536
#define GEMM_SMEM (3 * STG_BYTES)   // 192 KB

__global__ __launch_bounds__(512, 1) void gemm_tc(
    const __half* __restrict__ Ahi_g,
    const float* __restrict__ cosT, const float* __restrict__ sinT,
    float* __restrict__ out, int mode)
{
    extern __shared__ __align__(1024) char smem[];
    const uint32_t sb = smem_u32(smem);
    const int tid = threadIdx.x;
    const int wid = tid >> 5, lane = tid & 31;
    const int m0 = blockIdx.x * 256;
    const int by = blockIdx.y;

    int mat, n0;
    if (mode == 0) { mat = by >> 3; n0 = (by & 7) * 128; }
    else           { mat = 3;       n0 = by * 128; }
    const char* a_hi = (const char*)(Ahi_g + (size_t)m0 * D_);
    const char* b_hi = (const char*)(g_whi + (size_t)mat * D_ * D_ + (size_t)n0 * D_);
    const char* b_lo = (const char*)(g_wlo + (size_t)mat * D_ * D_ + (size_t)n0 * D_);

    const int l_kg = tid & 7;
    const int l_rb = tid >> 3;            // 0..63

    const int wm = (wid & 3) * 64;
    const int wn = (wid >> 2) * 32;
    const uint32_t a_row = wm + (lane & 15);
    const uint32_t a_co  = lane >> 4;
    const uint32_t a_sw  = a_row & 7;
    const uint32_t b_row = wn + (lane & 7) + ((lane >> 4) << 3);
    const uint32_t b_co  = (lane >> 3) & 1;
    const uint32_t b_sw  = b_row & 7;

    float acc[4][4][4];
    #pragma unroll
    for (int im = 0; im < 4; im++)
        #pragma unroll
        for (int in = 0; in < 4; in++)
            #pragma unroll
            for (int e = 0; e < 4; e++) acc[im][in][e] = 0.0f;

    auto load_stage = [&](int buf, int c) {
        const uint32_t sdst = sb + buf * STG_BYTES;
        const size_t kb = (size_t)c * 128 + l_kg * 16;
        #pragma unroll
        for (int p = 0; p < 4; p++) {                       // A-hi: 256 rows
            const int row = l_rb + p * 64;
            const size_t go = (size_t)row * 2048 + kb;
            const uint32_t so = row * 128 + ((l_kg ^ (row & 7)) << 4);
            cpasync16(sdst + STG_AH + so, a_hi + go);
        }
        #pragma unroll
        for (int p = 0; p < 2; p++) {                       // B hi+lo: 128 rows
            const int row = l_rb + p * 64;
            const size_t go = (size_t)row * 2048 + kb;
            const uint32_t so = row * 128 + ((l_kg ^ (row & 7)) << 4);
            cpasync16(sdst + STG_BH + so, b_hi + go);
            cpasync16(sdst + STG_BL + so, b_lo + go);
        }
    };

    load_stage(0, 0);  CP_COMMIT();
    load_stage(1, 1);  CP_COMMIT();

    for (int c = 0; c < 16; c++) {
        CP_WAIT(1);
        __syncthreads();
        const uint32_t s0 = sb + (c % 3) * STG_BYTES;

        #pragma unroll
        for (int ks = 0; ks < 4; ks++) {
            uint32_t ah[4][4], bh[2][4], bl[2][4];
            const uint32_t asw = ((2 * ks + a_co) ^ a_sw) << 4;
            const uint32_t bsw = ((2 * ks + b_co) ^ b_sw) << 4;
            #pragma unroll
            for (int im = 0; im < 4; im++)
                ldm_x4(ah[im], s0 + STG_AH + (a_row + im * 16) * 128 + asw);
            #pragma unroll
            for (int j = 0; j < 2; j++) {
                const uint32_t ro = (b_row + j * 16) * 128 + bsw;
                ldm_x4(bh[j], s0 + STG_BH + ro);
                ldm_x4(bl[j], s0 + STG_BL + ro);
            }
            #pragma unroll
            for (int im = 0; im < 4; im++)
                #pragma unroll
                for (int in = 0; in < 4; in++) {
                    mma16816h(acc[im][in], ah[im], &bh[in >> 1][(in & 1) * 2]);
                    mma16816h(acc[im][in], ah[im], &bl[in >> 1][(in & 1) * 2]);
                }
        }
        if (c + 2 < 16) load_stage((c + 2) % 3, c + 2);
        CP_COMMIT();
    }

    // ---- epilogue ----
    const int g = lane >> 2, q = lane & 3;
    #pragma unroll
    for (int im = 0; im < 4; im++) {
        #pragma unroll
        for (int half = 0; half < 2; half++) {
            const int m = m0 + wm + im * 16 + half * 8 + g;
            #pragma unroll
            for (int in = 0; in < 4; in++) {
                const int n = n0 + wn + in * 8 + q * 2;
                const float e0 = acc[im][in][half * 2 + 0];
                const float e1 = acc[im][in][half * 2 + 1];
                if (mode == 1) {
                    *(float2*)(out + (size_t)m * D_ + n) = make_float2(e0, e1);
                } else {
                    const int b = m >> 11, s = m & 2047;
                    const int h = n >> 6, hd = n & 63;
                    const size_t idx = ((size_t)(b * H_ + h) * S_ + s) * HD_ + hd;
                    if (mat == 2) {
                        *(__half2*)(g_vb + idx) = __floats2half2_rn(e0, e1);
                    } else {
                        const float cc = cosT[(size_t)s * HALF_ + (hd >> 1)];
                        const float ss = sinT[(size_t)s * HALF_ + (hd >> 1)];
                        float r0 = e0 * cc - e1 * ss;
                        float r1 = e0 * ss + e1 * cc;
                        if (mat == 0) {
                            r0 *= 0.125f; r1 *= 0.125f;   // fold 1/sqrt(HD)
                            __half h0, h1, l0, l1;
                            split_fp16(r0, h0, l0);
                            split_fp16(r1, h1, l1);
                            *(__half2*)(g_qh + idx) = __half2(h0, h1);
                            *(__half2*)(g_ql + idx) = __half2(l0, l1);
                        } else {
                            *(__half2*)(g_kh + idx) = __floats2half2_rn(r0, r1);
                        }
                    }
                }
            }
        }
    }
}

// ============================================================================
// Flash attention: BQ=128, BKV=64, 8 warps x 16 q-rows, 2 CTA/SM, 3-stage KV.
// Scores = (Qh+Ql)*Kh  (fp16 2-term on Q, K single; Q prescaled by 1/8).
// P,V fp16 (consistent-l). Epilogue writes fp16 -> g_ah [B,S,D].
// ============================================================================
#define FQ_HI 0
#define FQ_LO 16384
#define FKV0  32768
#define FSTG  16384
#define FKH   0
#define FVV   8192
#define FLASH_SMEM (32768 + 3 * FSTG)   // 80 KB

__global__ __launch_bounds__(256, 2) void flash_mma()
{
    extern __shared__ __align__(1024) char smem[];
    const uint32_t sb = smem_u32(smem);
    const int tid = threadIdx.x, wid = tid >> 5, lane = tid & 31;
    const int qb = (int)gridDim.x - 1 - (int)blockIdx.x;  // heavy blocks first
    const int bh = blockIdx.y;
    const int nc = 2 * qb + 2;
    const int wq0 = wid * 16;

    const char* qh_g = (const char*)g_qh + ((size_t)bh * S_ + (size_t)qb * 128) * 128;
    const char* ql_g = (const char*)g_ql + ((size_t)bh * S_ + (size_t)qb * 128) * 128;
    const char* kh_g = (const char*)g_kh + (size_t)bh * S_ * 128;
    const char* vv_g = (const char*)g_vb + (size_t)bh * S_ * 128;

    const int kg = tid & 7;
    #pragma unroll
    for (int p = 0; p < 4; p++) {
        const int row = (tid + p * 256) >> 3;   // 0..127
        const uint32_t so = row * 128 + ((kg ^ (row & 7)) << 4);
        const size_t go = (size_t)row * 128 + kg * 16;
        cpasync16(sb + FQ_HI + so, qh_g + go);
        cpasync16(sb + FQ_LO + so, ql_g + go);
    }
    CP_COMMIT();

    auto load_kv = [&](int st, int c) {
        const uint32_t base = sb + FKV0 + st * FSTG;
        #pragma unroll
        for (int p = 0; p < 2; p++) {
            const int row = (tid + p * 256) >> 3;   // 0..63
            const size_t go = ((size_t)c * 64 + row) * 128 + kg * 16;
            const uint32_t so = row * 128 + ((kg ^ (row & 7)) << 4);
            cpasync16(base + FKH + so, kh_g + go);
            cpasync16(base + FVV + so, vv_g + go);
        }
    };
    load_kv(0, 0);  CP_COMMIT();
    load_kv(1, 1);  CP_COMMIT();

    // Q fragments (wait for Q; kv0/kv1 may still be in flight)
    CP_WAIT(2);
    __syncthreads();
    uint32_t qh[4][4], ql[4][4];
    {
        const uint32_t a_row = wq0 + (lane & 15);
        const uint32_t a_co  = lane >> 4;
        #pragma unroll
        for (int ks = 0; ks < 4; ks++) {
            const uint32_t ro = a_row * 128 + (((2 * ks + a_co) ^ (a_row & 7)) << 4);
            ldm_x4(qh[ks], sb + FQ_HI + ro);
            ldm_x4(ql[ks], sb + FQ_LO + ro);
        }
    }

    const int g = lane >> 2, q2 = (lane & 3) * 2;
    float o[8][4];
    #pragma unroll
    for (int j = 0; j < 8; j++)
        #pragma unroll
        for (int e = 0; e < 4; e++) o[j][e] = 0.0f;
    float m0r = -1e30f, m1r = -1e30f, l0r = 0.0f, l1r = 0.0f;

    const uint32_t b_row = (lane & 7) + ((lane >> 4) << 3);
    const uint32_t b_co  = (lane >> 3) & 1;
    const uint32_t v_row = lane & 15;
    const uint32_t v_co  = lane >> 4;

    for (int c = 0; c < nc; c++) {
        CP_WAIT(1);
        __syncthreads();
        const uint32_t kbase = sb + FKV0 + (c % 3) * FSTG;

        // ---- scores: 16 x 64 = (Qh+Ql) x Kh ----
        float sc[8][4];
        #pragma unroll
        for (int j = 0; j < 8; j++)
            #pragma unroll
            for (int e = 0; e < 4; e++) sc[j][e] = 0.0f;

        #pragma unroll
        for (int ks = 0; ks < 4; ks++) {
            #pragma unroll
            for (int t = 0; t < 4; t++) {
                uint32_t kh4[4];
                const uint32_t row = b_row + 16 * t;
                const uint32_t ro = row * 128 + (((2 * ks + b_co) ^ (row & 7)) << 4);
                ldm_x4(kh4, kbase + FKH + ro);
                mma16816h(sc[2 * t],     qh[ks], &kh4[0]);
                mma16816h(sc[2 * t],     ql[ks], &kh4[0]);
                mma16816h(sc[2 * t + 1], qh[ks], &kh4[2]);
                mma16816h(sc[2 * t + 1], ql[ks], &kh4[2]);
            }
        }

        // ---- causal mask (diagonal chunks only) ----
        if (c >= 2 * qb) {
            const int kvb = c * 64;
            const int r0 = qb * 128 + wq0 + g, r1 = r0 + 8;
            #pragma unroll
            for (int j = 0; j < 8; j++) {
                const int col = kvb + 8 * j + q2;
                if (col     > r0) sc[j][0] = -1e30f;
                if (col + 1 > r0) sc[j][1] = -1e30f;
                if (col     > r1) sc[j][2] = -1e30f;
                if (col + 1 > r1) sc[j][3] = -1e30f;
            }
        }

        // ---- online softmax ----
        float mx0 = -1e30f, mx1 = -1e30f;
        #pragma unroll
        for (int j = 0; j < 8; j++) {
            mx0 = fmaxf(mx0, fmaxf(sc[j][0], sc[j][1]));
            mx1 = fmaxf(mx1, fmaxf(sc[j][2], sc[j][3]));
        }
        mx0 = fmaxf(mx0, __shfl_xor_sync(0xffffffffu, mx0, 1));
        mx0 = fmaxf(mx0, __shfl_xor_sync(0xffffffffu, mx0, 2));
        mx1 = fmaxf(mx1, __shfl_xor_sync(0xffffffffu, mx1, 1));
        mx1 = fmaxf(mx1, __shfl_xor_sync(0xffffffffu, mx1, 2));
        const float mn0 = fmaxf(m0r, mx0), mn1 = fmaxf(m1r, mx1);
        const float al0 = __expf(m0r - mn0), al1 = __expf(m1r - mn1);

        uint32_t pa[8][2];
        float rs0 = 0.0f, rs1 = 0.0f;
        #pragma unroll
        for (int j = 0; j < 8; j++) {
            const float p0 = __expf(sc[j][0] - mn0);
            const float p1 = __expf(sc[j][1] - mn0);
            const float p2 = __expf(sc[j][2] - mn1);
            const float p3 = __expf(sc[j][3] - mn1);
            __half2 h01 = __floats2half2_rn(p0, p1);
            __half2 h23 = __floats2half2_rn(p2, p3);
            pa[j][0] = *(uint32_t*)&h01;
            pa[j][1] = *(uint32_t*)&h23;
            rs0 += __low2float(h01) + __high2float(h01);
            rs1 += __low2float(h23) + __high2float(h23);
        }
        rs0 += __shfl_xor_sync(0xffffffffu, rs0, 1);
        rs0 += __shfl_xor_sync(0xffffffffu, rs0, 2);
        rs1 += __shfl_xor_sync(0xffffffffu, rs1, 1);
        rs1 += __shfl_xor_sync(0xffffffffu, rs1, 2);
        l0r = l0r * al0 + rs0;
        l1r = l1r * al1 + rs1;
        m0r = mn0; m1r = mn1;
        #pragma unroll
        for (int j = 0; j < 8; j++) {
            o[j][0] *= al0; o[j][1] *= al0;
            o[j][2] *= al1; o[j][3] *= al1;
        }

        // ---- PV: P (fp16 regs) x V^T (fp16, ldmatrix.trans) ----
        #pragma unroll
        for (int t = 0; t < 4; t++) {
            const uint32_t pA[4] = { pa[2*t][0], pa[2*t][1], pa[2*t+1][0], pa[2*t+1][1] };
            const uint32_t row = v_row + 16 * t;
            #pragma unroll
            for (int u = 0; u < 4; u++) {
                uint32_t vt[4];
                const uint32_t ro = row * 128 + (((2 * u + v_co) ^ (row & 7)) << 4);
                ldm_x4_t(vt, kbase + FVV + ro);
                mma16816h(o[2 * u],     pA, &vt[0]);
                mma16816h(o[2 * u + 1], pA, &vt[2]);
            }
        }

        if (c + 2 < nc) load_kv((c + 2) % 3, c + 2);
        CP_COMMIT();
    }

    // ---- epilogue: fp16 attn-out -> g_ah [B,S,D] ----
    const int b = bh >> 4, h = bh & 15;
    const float i0 = 1.0f / l0r, i1 = 1.0f / l1r;
    const int s0 = qb * 128 + wq0 + g, s1 = s0 + 8;
    const size_t r0 = ((size_t)b * S_ + s0) * D_ + h * HD_;
    const size_t r1 = ((size_t)b * S_ + s1) * D_ + h * HD_;
    #pragma unroll
    for (int j = 0; j < 8; j++) {
        const int col = 8 * j + q2;
        *(__half2*)(g_ah + r0 + col) = __floats2half2_rn(o[j][0] * i0, o[j][1] * i0);
        *(__half2*)(g_ah + r1 + col) = __floats2half2_rn(o[j][2] * i1, o[j][3] * i1);
    }
}

// ============================================================================
extern "C" void kernel_launch(void* const* d_in, const int* in_sizes, int n_in,
                              void* d_out, int out_size)
{
    (void)in_sizes; (void)n_in; (void)out_size;
    const float* x    = (const float*)d_in[0];
    const float* fcos = (const float*)d_in[1];
    const float* fsin = (const float*)d_in[2];
    const float* wq   = (const float*)d_in[3];
    const float* wk   = (const float*)d_in[4];
    const float* wv   = (const float*)d_in[5];
    const float* wo   = (const float*)d_in[6];
    float* out = (float*)d_out;

    __half* p_ah;
    cudaGetSymbolAddress((void**)&p_ah, g_ah);
    cudaFuncSetAttribute(gemm_tc,
                         cudaFuncAttributeMaxDynamicSharedMemorySize, GEMM_SMEM);
    cudaFuncSetAttribute(flash_mma,
                         cudaFuncAttributeMaxDynamicSharedMemorySize, FLASH_SMEM);

    const int n4x = M_ * D_ / 4;
    const int n4w = D_ * D_ / 4;

    // 0) fp32 -> fp16 conversions/splits (x + all 4 weights)
    convert_kernel<<<n4x / 256, 256>>>(x, p_ah, n4x);
    split4_kernel<<<dim3(n4w / 256, 4), 256>>>(wq, wk, wv, wo, n4w);

    // 1) QKV projections + RoPE -> attention operands (q hi/lo, k, v fp16)
    gemm_tc<<<dim3(M_ / 256, 24), 512, GEMM_SMEM>>>(p_ah, fcos, fsin, out, 0);

    // 2) causal flash attention (tensor cores) -> fp16 attn-out in g_ah
    flash_mma<<<dim3(S_ / 128, B_ * H_), 256, FLASH_SMEM>>>();

    // 3) output projection -> d_out
    gemm_tc<<<dim3(M_ / 256, 8), 512, GEMM_SMEM>>>(p_ah, fcos, fsin, out, 1);
}